// round 11
// baseline (speedup 1.0000x reference)
#include <cuda_runtime.h>
#include <cuda_fp16.h>
#include <math.h>

#define NN 50000
#define FF 128
#define CC 64
#define HH 4
#define EE 500000
#define GG 32
#define LL 4
#define NB 49   // scan blocks = ceil(NN/1024)

// ---------------- scratch (static device globals; no allocation allowed) ----------
__device__ __align__(16) float  g_h [NN*CC];
__device__ __align__(16) float  g_hn[NN*CC];
__device__ __align__(16) __half g_xl[NN*HH*CC];
__device__ __align__(16) __half g_xr[NN*HH*CC];
__device__ int   g_src[EE];
__device__ int   g_dst[EE];
__device__ int   g_csr[EE];
__device__ int   g_deg[NN];
__device__ int   g_incl[NN];
__device__ int   g_off[NN+1];
__device__ int   g_cur[NN];
__device__ int   g_part[64];
__device__ int   g_batch[NN];
__device__ int   g_is64;
__device__ float g_stats[4];     // two ping-pong slots of (sum, sumsq)

// ---------------- dtype detect: int64 edge_index has zero odd 32-bit words ----------
__global__ void detect_k(const int* __restrict__ ei32, int* __restrict__ flag) {
    __shared__ int nz;
    if (threadIdx.x == 0) nz = 0;
    __syncthreads();
    int v = ei32[threadIdx.x * 2 + 1];
    if (v != 0) atomicAdd(&nz, 1);
    __syncthreads();
    if (threadIdx.x == 0) *flag = (nz == 0) ? 1 : 0;
}

__device__ __forceinline__ int clampN(int v) {
    return v < 0 ? 0 : (v >= NN ? NN - 1 : v);
}

// ---------------- edge prep (convert + degree histogram + batch convert fused) -----
__global__ void convert_hist_k(const int* __restrict__ ei32, const int* __restrict__ flag,
                               int* __restrict__ src, int* __restrict__ dst,
                               int* __restrict__ deg,
                               const int* __restrict__ b32, int* __restrict__ bout) {
    int i = blockIdx.x * blockDim.x + threadIdx.x;
    if (i >= EE) return;
    int f = *flag;
    int s, d;
    if (f) { s = ei32[2 * i];      d = ei32[2 * (EE + i)]; }
    else   { s = ei32[i];          d = ei32[EE + i]; }
    s = clampN(s); d = clampN(d);
    src[i] = s;
    dst[i] = d;
    atomicAdd(&deg[d], 1);
    if (i < NN) {
        int v = f ? b32[2 * i] : b32[i];
        bout[i] = v < 0 ? 0 : (v >= GG ? GG - 1 : v);
    }
}

__global__ void scanA_k(const int* __restrict__ deg, int* __restrict__ incl, int* __restrict__ part) {
    __shared__ int s[1024];
    int i = blockIdx.x * 1024 + threadIdx.x;
    s[threadIdx.x] = (i < NN) ? deg[i] : 0;
    __syncthreads();
    for (int o = 1; o < 1024; o <<= 1) {
        int v = (threadIdx.x >= o) ? s[threadIdx.x - o] : 0;
        __syncthreads();
        s[threadIdx.x] += v;
        __syncthreads();
    }
    if (i < NN) incl[i] = s[threadIdx.x];
    if (threadIdx.x == 1023) part[blockIdx.x] = s[1023];
}

// scanC folds the part-prefix into each block.
__global__ void scanC_k(const int* __restrict__ incl, const int* __restrict__ part,
                        const int* __restrict__ deg, int* __restrict__ off, int* __restrict__ cur) {
    __shared__ int stmp[64];
    __shared__ int sbase;
    int t = threadIdx.x;
    if (t < 64) stmp[t] = (t < blockIdx.x) ? part[t] : 0;
    __syncthreads();
    if (t < 32) {
        int v = stmp[t] + stmp[t + 32];
        #pragma unroll
        for (int o = 16; o >= 1; o >>= 1) v += __shfl_xor_sync(0xffffffffu, v, o);
        if (t == 0) sbase = v;
    }
    __syncthreads();
    int i = blockIdx.x * 1024 + t;
    if (i < NN) {
        int start = incl[i] + sbase - deg[i];
        off[i] = start;
        cur[i] = start;
    }
    if (i == 0) off[NN] = EE;
}

__global__ void scatter_k(const int* __restrict__ src, const int* __restrict__ dst,
                          int* __restrict__ cur, int* __restrict__ csr) {
    int e = blockIdx.x * blockDim.x + threadIdx.x;
    if (e < EE) {
        int d = dst[e];
        int pos = atomicAdd(&cur[d], 1);
        csr[pos] = src[e];
    }
}

// ---------------- tf32 + selu helpers ----------------
__device__ __forceinline__ unsigned f2tf32(float v) {
    unsigned u;
    asm("cvt.rna.tf32.f32 %0, %1;" : "=r"(u) : "f"(v));
    return u;
}

__device__ __forceinline__ float selu_f(float x) {
    const float sc = 1.0507009873554805f, al = 1.6732632423543772f;
    return x > 0.f ? sc * x : sc * al * expm1f(x);
}

// ---------------- tf32 GEMM for layer projections: one block per 128-row chunk ------
// Stages A once (optional fused graph-norm + SELU), loops 8 output-column chunks.
// Block 0 zeroes this layer's stats slot for the following aggregate.
__global__ void __launch_bounds__(256) gemm_tf32_k(
    const float* __restrict__ A,
    const float* __restrict__ W0, const float* __restrict__ W1,
    const float* __restrict__ b0, const float* __restrict__ b1,
    __half* __restrict__ O0, __half* __restrict__ O1, int nrows,
    const float* __restrict__ normstats,
    const float* __restrict__ lw, const float* __restrict__ lb,
    float* __restrict__ zstats)
{
    __shared__ unsigned sA[128 * 68];

    const int t    = threadIdx.x;
    const int lane = t & 31;
    const int grp  = lane >> 2;
    const int qid  = lane & 3;
    const int wid  = t >> 5;
    const int warpM = wid & 3;
    const int warpN = wid >> 2;
    const int mbase = blockIdx.x * 128;

    if (blockIdx.x == 0 && t < 2) zstats[t] = 0.f;

    const int q = t & 15;
    float mean = 0.f, rstd = 1.f;
    float4 w4 = make_float4(1.f, 1.f, 1.f, 1.f), b4 = make_float4(0.f, 0.f, 0.f, 0.f);
    if (normstats) {
        const float invM = 1.f / ((float)NN * 64.f);
        mean = normstats[0] * invM;
        float var = normstats[1] * invM - mean * mean;
        rstd = 1.f / (sqrtf(fmaxf(var, 0.f)) + 1e-5f);
        w4 = *(const float4*)&lw[q * 4];
        b4 = *(const float4*)&lb[q * 4];
    }

    #pragma unroll
    for (int it = 0; it < 8; it++) {
        int idx = it * 256 + t;
        int r = idx >> 4;
        int gr = mbase + r;
        float4 v = make_float4(0.f, 0.f, 0.f, 0.f);
        if (gr < nrows) v = *(const float4*)&A[gr * 64 + q * 4];
        if (normstats) {
            v.x = selu_f((v.x - mean) * rstd * w4.x + b4.x);
            v.y = selu_f((v.y - mean) * rstd * w4.y + b4.y);
            v.z = selu_f((v.z - mean) * rstd * w4.z + b4.z);
            v.w = selu_f((v.w - mean) * rstd * w4.w + b4.w);
        }
        unsigned* dstp = &sA[r * 68 + q * 4];
        dstp[0] = f2tf32(v.x); dstp[1] = f2tf32(v.y);
        dstp[2] = f2tf32(v.z); dstp[3] = f2tf32(v.w);
    }
    __syncthreads();

    #pragma unroll 1
    for (int nc = 0; nc < 8; nc++) {
        const bool half1 = (nc >= 4);
        const float* Wb   = half1 ? W1 : W0;
        const float* bias = half1 ? b1 : b0;
        __half*      Ob   = half1 ? O1 : O0;
        const int nloc = (nc & 3) * 64 + warpN * 32;

        unsigned Breg[8][4][2];
        #pragma unroll
        for (int ks = 0; ks < 8; ks++) {
            #pragma unroll
            for (int nt = 0; nt < 4; nt++) {
                int col = nloc + nt * 8 + grp;
                Breg[ks][nt][0] = f2tf32(Wb[(ks * 8 + qid)     * 256 + col]);
                Breg[ks][nt][1] = f2tf32(Wb[(ks * 8 + qid + 4) * 256 + col]);
            }
        }

        float acc[2][4][4];
        #pragma unroll
        for (int mt = 0; mt < 2; mt++)
            #pragma unroll
            for (int nt = 0; nt < 4; nt++)
                #pragma unroll
                for (int c = 0; c < 4; c++) acc[mt][nt][c] = 0.f;

        #pragma unroll
        for (int ks = 0; ks < 8; ks++) {
            unsigned a[2][4];
            #pragma unroll
            for (int mt = 0; mt < 2; mt++) {
                int r0 = warpM * 32 + mt * 16 + grp;
                int c  = ks * 8 + qid;
                a[mt][0] = sA[r0 * 68 + c];
                a[mt][1] = sA[(r0 + 8) * 68 + c];
                a[mt][2] = sA[r0 * 68 + c + 4];
                a[mt][3] = sA[(r0 + 8) * 68 + c + 4];
            }
            #pragma unroll
            for (int mt = 0; mt < 2; mt++) {
                #pragma unroll
                for (int nt = 0; nt < 4; nt++) {
                    asm volatile(
                        "mma.sync.aligned.m16n8k8.row.col.f32.tf32.tf32.f32 "
                        "{%0,%1,%2,%3}, {%4,%5,%6,%7}, {%8,%9}, {%0,%1,%2,%3};"
                        : "+f"(acc[mt][nt][0]), "+f"(acc[mt][nt][1]),
                          "+f"(acc[mt][nt][2]), "+f"(acc[mt][nt][3])
                        : "r"(a[mt][0]), "r"(a[mt][1]), "r"(a[mt][2]), "r"(a[mt][3]),
                          "r"(Breg[ks][nt][0]), "r"(Breg[ks][nt][1]));
                }
            }
        }

        #pragma unroll
        for (int nt = 0; nt < 4; nt++) {
            int colw = nloc + nt * 8 + qid * 2;
            float bb0 = bias[colw], bb1 = bias[colw + 1];
            #pragma unroll
            for (int mt = 0; mt < 2; mt++) {
                int r0 = mbase + warpM * 32 + mt * 16 + grp;
                if (r0 < nrows)
                    *(__half2*)&Ob[r0 * 256 + colw] =
                        __floats2half2_rn(acc[mt][nt][0] + bb0, acc[mt][nt][1] + bb1);
                int r1 = r0 + 8;
                if (r1 < nrows)
                    *(__half2*)&Ob[r1 * 256 + colw] =
                        __floats2half2_rn(acc[mt][nt][2] + bb0, acc[mt][nt][3] + bb1);
            }
        }
    }
}

// ---------------- tf32 GEMM for initial projection (A[N,128] @ W[128,64]) ----------------
__global__ void __launch_bounds__(256) gemm_tf32_init_k(
    const float* __restrict__ A, const float* __restrict__ W,
    float* __restrict__ O, int nrows)
{
    __shared__ unsigned sA[128 * 68];

    const int t    = threadIdx.x;
    const int lane = t & 31;
    const int wid  = t >> 5;
    const int grp  = lane >> 2;
    const int qid  = lane & 3;
    const int warpM = wid & 3;
    const int warpN = wid >> 2;
    const int nloc = warpN * 32;
    const int mbase = blockIdx.x * 128;

    float acc[2][4][4];
    #pragma unroll
    for (int mt = 0; mt < 2; mt++)
        #pragma unroll
        for (int nt = 0; nt < 4; nt++)
            #pragma unroll
            for (int c = 0; c < 4; c++) acc[mt][nt][c] = 0.f;

    #pragma unroll
    for (int kc = 0; kc < 2; kc++) {
        unsigned Breg[8][4][2];
        #pragma unroll
        for (int ks = 0; ks < 8; ks++) {
            #pragma unroll
            for (int nt = 0; nt < 4; nt++) {
                int col = nloc + nt * 8 + grp;
                int row = kc * 64 + ks * 8;
                Breg[ks][nt][0] = f2tf32(W[(row + qid)     * 64 + col]);
                Breg[ks][nt][1] = f2tf32(W[(row + qid + 4) * 64 + col]);
            }
        }

        #pragma unroll
        for (int it = 0; it < 8; it++) {
            int idx = it * 256 + t;
            int r = idx >> 4, q = idx & 15;
            int gr = mbase + r;
            float4 v = make_float4(0.f, 0.f, 0.f, 0.f);
            if (gr < nrows) v = *(const float4*)&A[gr * 128 + kc * 64 + q * 4];
            unsigned* dstp = &sA[r * 68 + q * 4];
            dstp[0] = f2tf32(v.x); dstp[1] = f2tf32(v.y);
            dstp[2] = f2tf32(v.z); dstp[3] = f2tf32(v.w);
        }
        __syncthreads();

        #pragma unroll
        for (int ks = 0; ks < 8; ks++) {
            unsigned a[2][4];
            #pragma unroll
            for (int mt = 0; mt < 2; mt++) {
                int r0 = warpM * 32 + mt * 16 + grp;
                int c  = ks * 8 + qid;
                a[mt][0] = sA[r0 * 68 + c];
                a[mt][1] = sA[(r0 + 8) * 68 + c];
                a[mt][2] = sA[r0 * 68 + c + 4];
                a[mt][3] = sA[(r0 + 8) * 68 + c + 4];
            }
            #pragma unroll
            for (int mt = 0; mt < 2; mt++) {
                #pragma unroll
                for (int nt = 0; nt < 4; nt++) {
                    asm volatile(
                        "mma.sync.aligned.m16n8k8.row.col.f32.tf32.tf32.f32 "
                        "{%0,%1,%2,%3}, {%4,%5,%6,%7}, {%8,%9}, {%0,%1,%2,%3};"
                        : "+f"(acc[mt][nt][0]), "+f"(acc[mt][nt][1]),
                          "+f"(acc[mt][nt][2]), "+f"(acc[mt][nt][3])
                        : "r"(a[mt][0]), "r"(a[mt][1]), "r"(a[mt][2]), "r"(a[mt][3]),
                          "r"(Breg[ks][nt][0]), "r"(Breg[ks][nt][1]));
                }
            }
        }
        __syncthreads();
    }

    #pragma unroll
    for (int nt = 0; nt < 4; nt++) {
        int colw = nloc + nt * 8 + qid * 2;
        #pragma unroll
        for (int mt = 0; mt < 2; mt++) {
            int r0 = mbase + warpM * 32 + mt * 16 + grp;
            if (r0 < nrows)
                *(float2*)&O[r0 * 64 + colw] = make_float2(acc[mt][nt][0], acc[mt][nt][1]);
            int r1 = r0 + 8;
            if (r1 < nrows)
                *(float2*)&O[r1 * 64 + colw] = make_float2(acc[mt][nt][2], acc[mt][nt][3]);
        }
    }
}

// ---------------- GATv2 aggregate: 4 warps/block (finer tail granularity) ----------
__global__ void __launch_bounds__(128) aggregate_k(
    const __half* __restrict__ xl, const __half* __restrict__ xr,
    const int* __restrict__ off, const int* __restrict__ csr,
    const float* __restrict__ att, const float* __restrict__ cb,
    float* __restrict__ hn, float* __restrict__ stats)
{
    int warp = threadIdx.x >> 5, lane = threadIdx.x & 31;
    int i = blockIdx.x * 4 + warp;
    __shared__ float ssum[2];
    if (threadIdx.x < 2) ssum[threadIdx.x] = 0.f;
    __syncthreads();

    if (i < NN) {
        const float4* xl4 = (const float4*)xl;
        const float4* xr4 = (const float4*)xr;
        __half2 rr2[4];
        {
            float4 rv = xr4[i * 32 + lane];
            const __half2* hp = (const __half2*)&rv;
            #pragma unroll
            for (int k = 0; k < 4; k++) rr2[k] = hp[k];
        }
        int head = lane >> 3, cg = lane & 7;
        __half2 att2[4];
        #pragma unroll
        for (int k = 0; k < 4; k++)
            att2[k] = __floats2half2_rn(att[head * 64 + cg * 8 + 2 * k],
                                        att[head * 64 + cg * 8 + 2 * k + 1]);
        const __half2 c02 = __float2half2_rn(0.2f);

        float d = 0.f;
        __half2 acc2[4];
        #pragma unroll
        for (int k = 0; k < 4; k++) acc2[k] = __float2half2_rn(0.f);
        int e0 = off[i], e1 = off[i + 1];

        float4 sa, sb;
        if (e0 < e1)     sa = xl4[csr[e0] * 32 + lane];
        if (e0 + 1 < e1) sb = xl4[csr[e0 + 1] * 32 + lane];
        for (int e = e0; e < e1; e++) {
            float4 cur = sa;
            sa = sb;
            if (e + 2 < e1) sb = xl4[csr[e + 2] * 32 + lane];

            const __half2* x2 = (const __half2*)&cur;
            __half2 p2 = __float2half2_rn(0.f);
            #pragma unroll
            for (int k = 0; k < 4; k++) {
                __half2 v2 = __hadd2(x2[k], rr2[k]);
                __half2 lv = __hmax2(v2, __hmul2(v2, c02));
                p2 = __hfma2(lv, att2[k], p2);
            }
            float2 pf = __half22float2(p2);
            float p = pf.x + pf.y;
            p += __shfl_xor_sync(0xffffffffu, p, 4);
            p += __shfl_xor_sync(0xffffffffu, p, 2);
            p += __shfl_xor_sync(0xffffffffu, p, 1);
            float w = __expf(fminf(p, 60.f));
            d += w;
            __half2 w2 = __float2half2_rn(w);
            #pragma unroll
            for (int k = 0; k < 4; k++) acc2[k] = __hfma2(w2, x2[k], acc2[k]);
        }
        float inv = (d > 0.f) ? 1.f / d : 0.f;
        float o[8];
        #pragma unroll
        for (int k = 0; k < 4; k++) {
            float2 f = __half22float2(acc2[k]);
            o[2 * k]     = f.x * inv;
            o[2 * k + 1] = f.y * inv;
        }
        #pragma unroll
        for (int j = 0; j < 8; j++) o[j] += __shfl_xor_sync(0xffffffffu, o[j], 8);
        #pragma unroll
        for (int j = 0; j < 8; j++) o[j] += __shfl_xor_sync(0xffffffffu, o[j], 16);
        float ls = 0.f, lq = 0.f;
        #pragma unroll
        for (int j = 0; j < 8; j++) {
            o[j] = o[j] * 0.25f + cb[cg * 8 + j];
            ls += o[j];
            lq += o[j] * o[j];
        }
        if (lane < 8) {
            float4* hn4 = (float4*)hn;
            hn4[i * 16 + lane * 2]     = make_float4(o[0], o[1], o[2], o[3]);
            hn4[i * 16 + lane * 2 + 1] = make_float4(o[4], o[5], o[6], o[7]);
        }
        #pragma unroll
        for (int ofs = 16; ofs >= 1; ofs >>= 1) {
            ls += __shfl_xor_sync(0xffffffffu, ls, ofs);
            lq += __shfl_xor_sync(0xffffffffu, lq, ofs);
        }
        if (lane == 0) {
            atomicAdd(&ssum[0], ls * 0.25f);
            atomicAdd(&ssum[1], lq * 0.25f);
        }
    }
    __syncthreads();
    if (threadIdx.x == 0) {
        atomicAdd(&stats[0], ssum[0]);
        atomicAdd(&stats[1], ssum[1]);
    }
}

// ---------------- mean pool per graph (with fused final graph-norm + SELU) ---------
__device__ __forceinline__ int lbound_i(const int* a, int n, int key) {
    int lo = 0, hi = n;
    while (lo < hi) {
        int m = (lo + hi) >> 1;
        if (a[m] < key) lo = m + 1; else hi = m;
    }
    return lo;
}

__global__ void pool_k(const float* __restrict__ hn, const float* __restrict__ stats,
                       const float* __restrict__ lw, const float* __restrict__ lb,
                       const int* __restrict__ batch,
                       const float* __restrict__ Wh, const float* __restrict__ bh,
                       float* __restrict__ out)
{
    int g = blockIdx.x;
    __shared__ int slo, shi;
    __shared__ float sacc[4][64];
    __shared__ float sdot[64];
    int t = threadIdx.x;
    if (t == 0) {
        slo = lbound_i(batch, NN, g);
        shi = lbound_i(batch, NN, g + 1);
    }
    __syncthreads();
    const float invM = 1.f / ((float)NN * 64.f);
    float mean = stats[0] * invM;
    float var  = stats[1] * invM - mean * mean;
    float rstd = 1.f / (sqrtf(fmaxf(var, 0.f)) + 1e-5f);
    int lo = slo, hi = shi;
    int c = t & 63, slot = t >> 6;
    float wc = lw[c], bc = lb[c];
    float p = 0.f;
    for (int n = lo + slot; n < hi; n += 4)
        p += selu_f((hn[n * 64 + c] - mean) * rstd * wc + bc);
    sacc[slot][c] = p;
    __syncthreads();
    if (slot == 0) {
        float tot = sacc[0][c] + sacc[1][c] + sacc[2][c] + sacc[3][c];
        float cnt = (float)((hi - lo) > 1 ? (hi - lo) : 1);
        sdot[c] = (tot / cnt) * Wh[c];
    }
    __syncthreads();
    if (t < 32) {
        float v = sdot[t] + sdot[t + 32];
        #pragma unroll
        for (int o = 16; o >= 1; o >>= 1) v += __shfl_xor_sync(0xffffffffu, v, o);
        if (t == 0) out[g] = v + bh[0];
    }
}

// ---------------- launch ----------------
extern "C" void kernel_launch(void* const* d_in, const int* in_sizes, int n_in,
                              void* d_out, int out_size)
{
    const float* x     = (const float*)d_in[0];
    const int*   ei32  = (const int*)d_in[1];   // int32 or int64 (auto-detected)
    const int*   b32   = (const int*)d_in[2];
    const float* Wp    = (const float*)d_in[3];
    const float* Wl    = (const float*)d_in[4];
    const float* bl    = (const float*)d_in[5];
    const float* Wr    = (const float*)d_in[6];
    const float* br    = (const float*)d_in[7];
    const float* att   = (const float*)d_in[8];
    const float* cb    = (const float*)d_in[9];
    const float* lnw   = (const float*)d_in[10];
    const float* lnb   = (const float*)d_in[11];
    const float* Wh    = (const float*)d_in[12];
    const float* bh    = (const float*)d_in[13];
    float* out = (float*)d_out;

    float *p_h, *p_hn, *p_stats;
    __half *p_xl, *p_xr;
    int *p_src, *p_dst, *p_csr, *p_deg, *p_incl, *p_off, *p_cur, *p_part, *p_batch, *p_flag;
    cudaGetSymbolAddress((void**)&p_h,    g_h);
    cudaGetSymbolAddress((void**)&p_hn,   g_hn);
    cudaGetSymbolAddress((void**)&p_xl,   g_xl);
    cudaGetSymbolAddress((void**)&p_xr,   g_xr);
    cudaGetSymbolAddress((void**)&p_stats,g_stats);
    cudaGetSymbolAddress((void**)&p_src,  g_src);
    cudaGetSymbolAddress((void**)&p_dst,  g_dst);
    cudaGetSymbolAddress((void**)&p_csr,  g_csr);
    cudaGetSymbolAddress((void**)&p_deg,  g_deg);
    cudaGetSymbolAddress((void**)&p_incl, g_incl);
    cudaGetSymbolAddress((void**)&p_off,  g_off);
    cudaGetSymbolAddress((void**)&p_cur,  g_cur);
    cudaGetSymbolAddress((void**)&p_part, g_part);
    cudaGetSymbolAddress((void**)&p_batch,g_batch);
    cudaGetSymbolAddress((void**)&p_flag, g_is64);

    // dtype detect + CSR build (per call; edge_index is an input)
    detect_k<<<1, 256>>>(ei32, p_flag);
    cudaMemsetAsync(p_deg, 0, NN * sizeof(int));
    convert_hist_k<<<(EE + 255) / 256, 256>>>(ei32, p_flag, p_src, p_dst, p_deg, b32, p_batch);
    scanA_k<<<NB, 1024>>>(p_deg, p_incl, p_part);
    scanC_k<<<NB, 1024>>>(p_incl, p_part, p_deg, p_off, p_cur);
    scatter_k<<<(EE + 255) / 256, 256>>>(p_src, p_dst, p_cur, p_csr);

    // initial projection: h = x @ Wp (tf32 tensor cores)
    gemm_tf32_init_k<<<(NN + 127) / 128, 256>>>(x, Wp, p_h, NN);

    const int NCHUNK = (NN + 127) / 128;
    for (int l = 0; l < LL; l++) {
        float* slotCur  = p_stats + (l & 1) * 2;
        const float* slotPrev = p_stats + ((l + 1) & 1) * 2;
        const float* Ain = (l == 0) ? p_h : p_hn;
        gemm_tf32_k<<<NCHUNK, 256>>>(
            Ain, Wl + l * 64 * 256, Wr + l * 64 * 256,
            bl + l * 256, br + l * 256, p_xl, p_xr, NN,
            (l == 0) ? nullptr : slotPrev,
            (l == 0) ? nullptr : (lnw + (l - 1) * CC),
            (l == 0) ? nullptr : (lnb + (l - 1) * CC),
            slotCur);
        aggregate_k<<<(NN + 3) / 4, 128>>>(p_xl, p_xr, p_off, p_csr,
                                           att + l * HH * CC, cb + l * CC, p_hn, slotCur);
    }

    // pool with fused final graph-norm + SELU
    pool_k<<<GG, 256>>>(p_hn, p_stats + ((LL - 1) & 1) * 2,
                        lnw + (LL - 1) * CC, lnb + (LL - 1) * CC,
                        p_batch, Wh, bh, out);
}

// round 12
// speedup vs baseline: 1.0019x; 1.0019x over previous
#include <cuda_runtime.h>
#include <cuda_fp16.h>
#include <math.h>

#define NN 50000
#define FF 128
#define CC 64
#define HH 4
#define EE 500000
#define GG 32
#define LL 4
#define NB 49   // scan blocks = ceil(NN/1024)

// ---------------- scratch (static device globals; no allocation allowed) ----------
__device__ __align__(16) float  g_h [NN*CC];
__device__ __align__(16) float  g_hn[NN*CC];
__device__ __align__(16) __half g_xl[NN*HH*CC];
__device__ __align__(16) __half g_xr[NN*HH*CC];
__device__ int   g_src[EE];
__device__ int   g_dst[EE];
__device__ int   g_csr[EE];
__device__ int   g_deg[NN];
__device__ int   g_incl[NN];
__device__ int   g_off[NN+1];
__device__ int   g_cur[NN];
__device__ int   g_part[64];
__device__ int   g_batch[NN];
__device__ int   g_is64;
__device__ float g_stats[4];     // two ping-pong slots of (sum, sumsq)

// ---------------- dtype detect: int64 edge_index has zero odd 32-bit words ----------
__global__ void detect_k(const int* __restrict__ ei32, int* __restrict__ flag) {
    __shared__ int nz;
    if (threadIdx.x == 0) nz = 0;
    __syncthreads();
    int v = ei32[threadIdx.x * 2 + 1];
    if (v != 0) atomicAdd(&nz, 1);
    __syncthreads();
    if (threadIdx.x == 0) *flag = (nz == 0) ? 1 : 0;
}

__device__ __forceinline__ int clampN(int v) {
    return v < 0 ? 0 : (v >= NN ? NN - 1 : v);
}

// ---------------- edge prep (convert + degree histogram + batch convert fused) -----
__global__ void convert_hist_k(const int* __restrict__ ei32, const int* __restrict__ flag,
                               int* __restrict__ src, int* __restrict__ dst,
                               int* __restrict__ deg,
                               const int* __restrict__ b32, int* __restrict__ bout) {
    int i = blockIdx.x * blockDim.x + threadIdx.x;
    if (i >= EE) return;
    int f = *flag;
    int s, d;
    if (f) { s = ei32[2 * i];      d = ei32[2 * (EE + i)]; }
    else   { s = ei32[i];          d = ei32[EE + i]; }
    s = clampN(s); d = clampN(d);
    src[i] = s;
    dst[i] = d;
    atomicAdd(&deg[d], 1);
    if (i < NN) {
        int v = f ? b32[2 * i] : b32[i];
        bout[i] = v < 0 ? 0 : (v >= GG ? GG - 1 : v);
    }
}

__global__ void scanA_k(const int* __restrict__ deg, int* __restrict__ incl, int* __restrict__ part) {
    __shared__ int s[1024];
    int i = blockIdx.x * 1024 + threadIdx.x;
    s[threadIdx.x] = (i < NN) ? deg[i] : 0;
    __syncthreads();
    for (int o = 1; o < 1024; o <<= 1) {
        int v = (threadIdx.x >= o) ? s[threadIdx.x - o] : 0;
        __syncthreads();
        s[threadIdx.x] += v;
        __syncthreads();
    }
    if (i < NN) incl[i] = s[threadIdx.x];
    if (threadIdx.x == 1023) part[blockIdx.x] = s[1023];
}

// scanC folds the part-prefix into each block.
__global__ void scanC_k(const int* __restrict__ incl, const int* __restrict__ part,
                        const int* __restrict__ deg, int* __restrict__ off, int* __restrict__ cur) {
    __shared__ int stmp[64];
    __shared__ int sbase;
    int t = threadIdx.x;
    if (t < 64) stmp[t] = (t < blockIdx.x) ? part[t] : 0;
    __syncthreads();
    if (t < 32) {
        int v = stmp[t] + stmp[t + 32];
        #pragma unroll
        for (int o = 16; o >= 1; o >>= 1) v += __shfl_xor_sync(0xffffffffu, v, o);
        if (t == 0) sbase = v;
    }
    __syncthreads();
    int i = blockIdx.x * 1024 + t;
    if (i < NN) {
        int start = incl[i] + sbase - deg[i];
        off[i] = start;
        cur[i] = start;
    }
    if (i == 0) off[NN] = EE;
}

__global__ void scatter_k(const int* __restrict__ src, const int* __restrict__ dst,
                          int* __restrict__ cur, int* __restrict__ csr) {
    int e = blockIdx.x * blockDim.x + threadIdx.x;
    if (e < EE) {
        int d = dst[e];
        int pos = atomicAdd(&cur[d], 1);
        csr[pos] = src[e];
    }
}

// ---------------- tf32 + selu helpers ----------------
__device__ __forceinline__ unsigned f2tf32(float v) {
    unsigned u;
    asm("cvt.rna.tf32.f32 %0, %1;" : "=r"(u) : "f"(v));
    return u;
}

__device__ __forceinline__ float selu_f(float x) {
    const float sc = 1.0507009873554805f, al = 1.6732632423543772f;
    return x > 0.f ? sc * x : sc * al * expm1f(x);
}

// ---------------- tf32 GEMM for layer projections: one block per 128-row chunk ------
// Stages A once (optional fused graph-norm + SELU), loops 8 output-column chunks.
// Block 0 zeroes this layer's stats slot for the following aggregate.
__global__ void __launch_bounds__(256) gemm_tf32_k(
    const float* __restrict__ A,
    const float* __restrict__ W0, const float* __restrict__ W1,
    const float* __restrict__ b0, const float* __restrict__ b1,
    __half* __restrict__ O0, __half* __restrict__ O1, int nrows,
    const float* __restrict__ normstats,
    const float* __restrict__ lw, const float* __restrict__ lb,
    float* __restrict__ zstats)
{
    __shared__ unsigned sA[128 * 68];

    const int t    = threadIdx.x;
    const int lane = t & 31;
    const int grp  = lane >> 2;
    const int qid  = lane & 3;
    const int wid  = t >> 5;
    const int warpM = wid & 3;
    const int warpN = wid >> 2;
    const int mbase = blockIdx.x * 128;

    if (blockIdx.x == 0 && t < 2) zstats[t] = 0.f;

    const int q = t & 15;
    float mean = 0.f, rstd = 1.f;
    float4 w4 = make_float4(1.f, 1.f, 1.f, 1.f), b4 = make_float4(0.f, 0.f, 0.f, 0.f);
    if (normstats) {
        const float invM = 1.f / ((float)NN * 64.f);
        mean = normstats[0] * invM;
        float var = normstats[1] * invM - mean * mean;
        rstd = 1.f / (sqrtf(fmaxf(var, 0.f)) + 1e-5f);
        w4 = *(const float4*)&lw[q * 4];
        b4 = *(const float4*)&lb[q * 4];
    }

    #pragma unroll
    for (int it = 0; it < 8; it++) {
        int idx = it * 256 + t;
        int r = idx >> 4;
        int gr = mbase + r;
        float4 v = make_float4(0.f, 0.f, 0.f, 0.f);
        if (gr < nrows) v = *(const float4*)&A[gr * 64 + q * 4];
        if (normstats) {
            v.x = selu_f((v.x - mean) * rstd * w4.x + b4.x);
            v.y = selu_f((v.y - mean) * rstd * w4.y + b4.y);
            v.z = selu_f((v.z - mean) * rstd * w4.z + b4.z);
            v.w = selu_f((v.w - mean) * rstd * w4.w + b4.w);
        }
        unsigned* dstp = &sA[r * 68 + q * 4];
        dstp[0] = f2tf32(v.x); dstp[1] = f2tf32(v.y);
        dstp[2] = f2tf32(v.z); dstp[3] = f2tf32(v.w);
    }
    __syncthreads();

    #pragma unroll 1
    for (int nc = 0; nc < 8; nc++) {
        const bool half1 = (nc >= 4);
        const float* Wb   = half1 ? W1 : W0;
        const float* bias = half1 ? b1 : b0;
        __half*      Ob   = half1 ? O1 : O0;
        const int nloc = (nc & 3) * 64 + warpN * 32;

        unsigned Breg[8][4][2];
        #pragma unroll
        for (int ks = 0; ks < 8; ks++) {
            #pragma unroll
            for (int nt = 0; nt < 4; nt++) {
                int col = nloc + nt * 8 + grp;
                Breg[ks][nt][0] = f2tf32(Wb[(ks * 8 + qid)     * 256 + col]);
                Breg[ks][nt][1] = f2tf32(Wb[(ks * 8 + qid + 4) * 256 + col]);
            }
        }

        float acc[2][4][4];
        #pragma unroll
        for (int mt = 0; mt < 2; mt++)
            #pragma unroll
            for (int nt = 0; nt < 4; nt++)
                #pragma unroll
                for (int c = 0; c < 4; c++) acc[mt][nt][c] = 0.f;

        #pragma unroll
        for (int ks = 0; ks < 8; ks++) {
            unsigned a[2][4];
            #pragma unroll
            for (int mt = 0; mt < 2; mt++) {
                int r0 = warpM * 32 + mt * 16 + grp;
                int c  = ks * 8 + qid;
                a[mt][0] = sA[r0 * 68 + c];
                a[mt][1] = sA[(r0 + 8) * 68 + c];
                a[mt][2] = sA[r0 * 68 + c + 4];
                a[mt][3] = sA[(r0 + 8) * 68 + c + 4];
            }
            #pragma unroll
            for (int mt = 0; mt < 2; mt++) {
                #pragma unroll
                for (int nt = 0; nt < 4; nt++) {
                    asm volatile(
                        "mma.sync.aligned.m16n8k8.row.col.f32.tf32.tf32.f32 "
                        "{%0,%1,%2,%3}, {%4,%5,%6,%7}, {%8,%9}, {%0,%1,%2,%3};"
                        : "+f"(acc[mt][nt][0]), "+f"(acc[mt][nt][1]),
                          "+f"(acc[mt][nt][2]), "+f"(acc[mt][nt][3])
                        : "r"(a[mt][0]), "r"(a[mt][1]), "r"(a[mt][2]), "r"(a[mt][3]),
                          "r"(Breg[ks][nt][0]), "r"(Breg[ks][nt][1]));
                }
            }
        }

        #pragma unroll
        for (int nt = 0; nt < 4; nt++) {
            int colw = nloc + nt * 8 + qid * 2;
            float bb0 = bias[colw], bb1 = bias[colw + 1];
            #pragma unroll
            for (int mt = 0; mt < 2; mt++) {
                int r0 = mbase + warpM * 32 + mt * 16 + grp;
                if (r0 < nrows)
                    *(__half2*)&Ob[r0 * 256 + colw] =
                        __floats2half2_rn(acc[mt][nt][0] + bb0, acc[mt][nt][1] + bb1);
                int r1 = r0 + 8;
                if (r1 < nrows)
                    *(__half2*)&Ob[r1 * 256 + colw] =
                        __floats2half2_rn(acc[mt][nt][2] + bb0, acc[mt][nt][3] + bb1);
            }
        }
    }
}

// ---------------- tf32 GEMM for initial projection (A[N,128] @ W[128,64]) ----------------
__global__ void __launch_bounds__(256) gemm_tf32_init_k(
    const float* __restrict__ A, const float* __restrict__ W,
    float* __restrict__ O, int nrows)
{
    __shared__ unsigned sA[128 * 68];

    const int t    = threadIdx.x;
    const int lane = t & 31;
    const int wid  = t >> 5;
    const int grp  = lane >> 2;
    const int qid  = lane & 3;
    const int warpM = wid & 3;
    const int warpN = wid >> 2;
    const int nloc = warpN * 32;
    const int mbase = blockIdx.x * 128;

    float acc[2][4][4];
    #pragma unroll
    for (int mt = 0; mt < 2; mt++)
        #pragma unroll
        for (int nt = 0; nt < 4; nt++)
            #pragma unroll
            for (int c = 0; c < 4; c++) acc[mt][nt][c] = 0.f;

    #pragma unroll
    for (int kc = 0; kc < 2; kc++) {
        unsigned Breg[8][4][2];
        #pragma unroll
        for (int ks = 0; ks < 8; ks++) {
            #pragma unroll
            for (int nt = 0; nt < 4; nt++) {
                int col = nloc + nt * 8 + grp;
                int row = kc * 64 + ks * 8;
                Breg[ks][nt][0] = f2tf32(W[(row + qid)     * 64 + col]);
                Breg[ks][nt][1] = f2tf32(W[(row + qid + 4) * 64 + col]);
            }
        }

        #pragma unroll
        for (int it = 0; it < 8; it++) {
            int idx = it * 256 + t;
            int r = idx >> 4, q = idx & 15;
            int gr = mbase + r;
            float4 v = make_float4(0.f, 0.f, 0.f, 0.f);
            if (gr < nrows) v = *(const float4*)&A[gr * 128 + kc * 64 + q * 4];
            unsigned* dstp = &sA[r * 68 + q * 4];
            dstp[0] = f2tf32(v.x); dstp[1] = f2tf32(v.y);
            dstp[2] = f2tf32(v.z); dstp[3] = f2tf32(v.w);
        }
        __syncthreads();

        #pragma unroll
        for (int ks = 0; ks < 8; ks++) {
            unsigned a[2][4];
            #pragma unroll
            for (int mt = 0; mt < 2; mt++) {
                int r0 = warpM * 32 + mt * 16 + grp;
                int c  = ks * 8 + qid;
                a[mt][0] = sA[r0 * 68 + c];
                a[mt][1] = sA[(r0 + 8) * 68 + c];
                a[mt][2] = sA[r0 * 68 + c + 4];
                a[mt][3] = sA[(r0 + 8) * 68 + c + 4];
            }
            #pragma unroll
            for (int mt = 0; mt < 2; mt++) {
                #pragma unroll
                for (int nt = 0; nt < 4; nt++) {
                    asm volatile(
                        "mma.sync.aligned.m16n8k8.row.col.f32.tf32.tf32.f32 "
                        "{%0,%1,%2,%3}, {%4,%5,%6,%7}, {%8,%9}, {%0,%1,%2,%3};"
                        : "+f"(acc[mt][nt][0]), "+f"(acc[mt][nt][1]),
                          "+f"(acc[mt][nt][2]), "+f"(acc[mt][nt][3])
                        : "r"(a[mt][0]), "r"(a[mt][1]), "r"(a[mt][2]), "r"(a[mt][3]),
                          "r"(Breg[ks][nt][0]), "r"(Breg[ks][nt][1]));
                }
            }
        }
        __syncthreads();
    }

    #pragma unroll
    for (int nt = 0; nt < 4; nt++) {
        int colw = nloc + nt * 8 + qid * 2;
        #pragma unroll
        for (int mt = 0; mt < 2; mt++) {
            int r0 = mbase + warpM * 32 + mt * 16 + grp;
            if (r0 < nrows)
                *(float2*)&O[r0 * 64 + colw] = make_float2(acc[mt][nt][0], acc[mt][nt][1]);
            int r1 = r0 + 8;
            if (r1 < nrows)
                *(float2*)&O[r1 * 64 + colw] = make_float2(acc[mt][nt][2], acc[mt][nt][3]);
        }
    }
}

// ---------------- GATv2 aggregate: 8 warps/block (Round-10 proven config) ----------
__global__ void __launch_bounds__(256) aggregate_k(
    const __half* __restrict__ xl, const __half* __restrict__ xr,
    const int* __restrict__ off, const int* __restrict__ csr,
    const float* __restrict__ att, const float* __restrict__ cb,
    float* __restrict__ hn, float* __restrict__ stats)
{
    int warp = threadIdx.x >> 5, lane = threadIdx.x & 31;
    int i = blockIdx.x * 8 + warp;
    __shared__ float ssum[2];
    if (threadIdx.x < 2) ssum[threadIdx.x] = 0.f;
    __syncthreads();

    if (i < NN) {
        const float4* xl4 = (const float4*)xl;
        const float4* xr4 = (const float4*)xr;
        __half2 rr2[4];
        {
            float4 rv = xr4[i * 32 + lane];
            const __half2* hp = (const __half2*)&rv;
            #pragma unroll
            for (int k = 0; k < 4; k++) rr2[k] = hp[k];
        }
        int head = lane >> 3, cg = lane & 7;
        __half2 att2[4];
        #pragma unroll
        for (int k = 0; k < 4; k++)
            att2[k] = __floats2half2_rn(att[head * 64 + cg * 8 + 2 * k],
                                        att[head * 64 + cg * 8 + 2 * k + 1]);
        const __half2 c02 = __float2half2_rn(0.2f);

        float d = 0.f;
        __half2 acc2[4];
        #pragma unroll
        for (int k = 0; k < 4; k++) acc2[k] = __float2half2_rn(0.f);
        int e0 = off[i], e1 = off[i + 1];

        float4 sa, sb;
        if (e0 < e1)     sa = xl4[csr[e0] * 32 + lane];
        if (e0 + 1 < e1) sb = xl4[csr[e0 + 1] * 32 + lane];
        for (int e = e0; e < e1; e++) {
            float4 cur = sa;
            sa = sb;
            if (e + 2 < e1) sb = xl4[csr[e + 2] * 32 + lane];

            const __half2* x2 = (const __half2*)&cur;
            __half2 p2 = __float2half2_rn(0.f);
            #pragma unroll
            for (int k = 0; k < 4; k++) {
                __half2 v2 = __hadd2(x2[k], rr2[k]);
                __half2 lv = __hmax2(v2, __hmul2(v2, c02));
                p2 = __hfma2(lv, att2[k], p2);
            }
            float2 pf = __half22float2(p2);
            float p = pf.x + pf.y;
            p += __shfl_xor_sync(0xffffffffu, p, 4);
            p += __shfl_xor_sync(0xffffffffu, p, 2);
            p += __shfl_xor_sync(0xffffffffu, p, 1);
            float w = __expf(fminf(p, 60.f));
            d += w;
            __half2 w2 = __float2half2_rn(w);
            #pragma unroll
            for (int k = 0; k < 4; k++) acc2[k] = __hfma2(w2, x2[k], acc2[k]);
        }
        float inv = (d > 0.f) ? 1.f / d : 0.f;
        float o[8];
        #pragma unroll
        for (int k = 0; k < 4; k++) {
            float2 f = __half22float2(acc2[k]);
            o[2 * k]     = f.x * inv;
            o[2 * k + 1] = f.y * inv;
        }
        #pragma unroll
        for (int j = 0; j < 8; j++) o[j] += __shfl_xor_sync(0xffffffffu, o[j], 8);
        #pragma unroll
        for (int j = 0; j < 8; j++) o[j] += __shfl_xor_sync(0xffffffffu, o[j], 16);
        float ls = 0.f, lq = 0.f;
        #pragma unroll
        for (int j = 0; j < 8; j++) {
            o[j] = o[j] * 0.25f + cb[cg * 8 + j];
            ls += o[j];
            lq += o[j] * o[j];
        }
        if (lane < 8) {
            float4* hn4 = (float4*)hn;
            hn4[i * 16 + lane * 2]     = make_float4(o[0], o[1], o[2], o[3]);
            hn4[i * 16 + lane * 2 + 1] = make_float4(o[4], o[5], o[6], o[7]);
        }
        #pragma unroll
        for (int ofs = 16; ofs >= 1; ofs >>= 1) {
            ls += __shfl_xor_sync(0xffffffffu, ls, ofs);
            lq += __shfl_xor_sync(0xffffffffu, lq, ofs);
        }
        if (lane == 0) {
            atomicAdd(&ssum[0], ls * 0.25f);
            atomicAdd(&ssum[1], lq * 0.25f);
        }
    }
    __syncthreads();
    if (threadIdx.x == 0) {
        atomicAdd(&stats[0], ssum[0]);
        atomicAdd(&stats[1], ssum[1]);
    }
}

// ---------------- mean pool per graph (with fused final graph-norm + SELU) ---------
__device__ __forceinline__ int lbound_i(const int* a, int n, int key) {
    int lo = 0, hi = n;
    while (lo < hi) {
        int m = (lo + hi) >> 1;
        if (a[m] < key) lo = m + 1; else hi = m;
    }
    return lo;
}

__global__ void pool_k(const float* __restrict__ hn, const float* __restrict__ stats,
                       const float* __restrict__ lw, const float* __restrict__ lb,
                       const int* __restrict__ batch,
                       const float* __restrict__ Wh, const float* __restrict__ bh,
                       float* __restrict__ out)
{
    int g = blockIdx.x;
    __shared__ int slo, shi;
    __shared__ float sacc[4][64];
    __shared__ float sdot[64];
    int t = threadIdx.x;
    if (t == 0) {
        slo = lbound_i(batch, NN, g);
        shi = lbound_i(batch, NN, g + 1);
    }
    __syncthreads();
    const float invM = 1.f / ((float)NN * 64.f);
    float mean = stats[0] * invM;
    float var  = stats[1] * invM - mean * mean;
    float rstd = 1.f / (sqrtf(fmaxf(var, 0.f)) + 1e-5f);
    int lo = slo, hi = shi;
    int c = t & 63, slot = t >> 6;
    float wc = lw[c], bc = lb[c];
    float p = 0.f;
    for (int n = lo + slot; n < hi; n += 4)
        p += selu_f((hn[n * 64 + c] - mean) * rstd * wc + bc);
    sacc[slot][c] = p;
    __syncthreads();
    if (slot == 0) {
        float tot = sacc[0][c] + sacc[1][c] + sacc[2][c] + sacc[3][c];
        float cnt = (float)((hi - lo) > 1 ? (hi - lo) : 1);
        sdot[c] = (tot / cnt) * Wh[c];
    }
    __syncthreads();
    if (t < 32) {
        float v = sdot[t] + sdot[t + 32];
        #pragma unroll
        for (int o = 16; o >= 1; o >>= 1) v += __shfl_xor_sync(0xffffffffu, v, o);
        if (t == 0) out[g] = v + bh[0];
    }
}

// ---------------- launch ----------------
extern "C" void kernel_launch(void* const* d_in, const int* in_sizes, int n_in,
                              void* d_out, int out_size)
{
    const float* x     = (const float*)d_in[0];
    const int*   ei32  = (const int*)d_in[1];   // int32 or int64 (auto-detected)
    const int*   b32   = (const int*)d_in[2];
    const float* Wp    = (const float*)d_in[3];
    const float* Wl    = (const float*)d_in[4];
    const float* bl    = (const float*)d_in[5];
    const float* Wr    = (const float*)d_in[6];
    const float* br    = (const float*)d_in[7];
    const float* att   = (const float*)d_in[8];
    const float* cb    = (const float*)d_in[9];
    const float* lnw   = (const float*)d_in[10];
    const float* lnb   = (const float*)d_in[11];
    const float* Wh    = (const float*)d_in[12];
    const float* bh    = (const float*)d_in[13];
    float* out = (float*)d_out;

    float *p_h, *p_hn, *p_stats;
    __half *p_xl, *p_xr;
    int *p_src, *p_dst, *p_csr, *p_deg, *p_incl, *p_off, *p_cur, *p_part, *p_batch, *p_flag;
    cudaGetSymbolAddress((void**)&p_h,    g_h);
    cudaGetSymbolAddress((void**)&p_hn,   g_hn);
    cudaGetSymbolAddress((void**)&p_xl,   g_xl);
    cudaGetSymbolAddress((void**)&p_xr,   g_xr);
    cudaGetSymbolAddress((void**)&p_stats,g_stats);
    cudaGetSymbolAddress((void**)&p_src,  g_src);
    cudaGetSymbolAddress((void**)&p_dst,  g_dst);
    cudaGetSymbolAddress((void**)&p_csr,  g_csr);
    cudaGetSymbolAddress((void**)&p_deg,  g_deg);
    cudaGetSymbolAddress((void**)&p_incl, g_incl);
    cudaGetSymbolAddress((void**)&p_off,  g_off);
    cudaGetSymbolAddress((void**)&p_cur,  g_cur);
    cudaGetSymbolAddress((void**)&p_part, g_part);
    cudaGetSymbolAddress((void**)&p_batch,g_batch);
    cudaGetSymbolAddress((void**)&p_flag, g_is64);

    // dtype detect + CSR build (per call; edge_index is an input)
    detect_k<<<1, 256>>>(ei32, p_flag);
    cudaMemsetAsync(p_deg, 0, NN * sizeof(int));
    convert_hist_k<<<(EE + 255) / 256, 256>>>(ei32, p_flag, p_src, p_dst, p_deg, b32, p_batch);
    scanA_k<<<NB, 1024>>>(p_deg, p_incl, p_part);
    scanC_k<<<NB, 1024>>>(p_incl, p_part, p_deg, p_off, p_cur);
    scatter_k<<<(EE + 255) / 256, 256>>>(p_src, p_dst, p_cur, p_csr);

    // initial projection: h = x @ Wp (tf32 tensor cores)
    gemm_tf32_init_k<<<(NN + 127) / 128, 256>>>(x, Wp, p_h, NN);

    const int NCHUNK = (NN + 127) / 128;
    for (int l = 0; l < LL; l++) {
        float* slotCur  = p_stats + (l & 1) * 2;
        const float* slotPrev = p_stats + ((l + 1) & 1) * 2;
        const float* Ain = (l == 0) ? p_h : p_hn;
        gemm_tf32_k<<<NCHUNK, 256>>>(
            Ain, Wl + l * 64 * 256, Wr + l * 64 * 256,
            bl + l * 256, br + l * 256, p_xl, p_xr, NN,
            (l == 0) ? nullptr : slotPrev,
            (l == 0) ? nullptr : (lnw + (l - 1) * CC),
            (l == 0) ? nullptr : (lnb + (l - 1) * CC),
            slotCur);
        aggregate_k<<<(NN + 7) / 8, 256>>>(p_xl, p_xr, p_off, p_csr,
                                           att + l * HH * CC, cb + l * CC, p_hn, slotCur);
    }

    // pool with fused final graph-norm + SELU
    pool_k<<<GG, 256>>>(p_hn, p_stats + ((LL - 1) & 1) * 2,
                        lnw + (LL - 1) * CC, lnb + (LL - 1) * CC,
                        p_batch, Wh, bh, out);
}

// round 13
// speedup vs baseline: 1.0878x; 1.0857x over previous
#include <cuda_runtime.h>
#include <cuda_fp16.h>
#include <math.h>

#define NN 50000
#define FF 128
#define CC 64
#define HH 4
#define EE 500000
#define GG 32
#define LL 4
#define NB 49   // scan blocks = ceil(NN/1024)

// ---------------- scratch (static device globals; no allocation allowed) ----------
__device__ __align__(16) float  g_h [NN*CC];
__device__ __align__(16) float  g_hn[NN*CC];
__device__ __align__(16) __half g_xl[NN*HH*CC];
__device__ __align__(16) __half g_xr[NN*HH*CC];
__device__ int   g_src[EE];
__device__ int   g_dst[EE];
__device__ int   g_csr[EE];
__device__ int   g_deg[NN];
__device__ int   g_incl[NN];
__device__ int   g_off[NN+1];
__device__ int   g_cur[NN];
__device__ int   g_part[64];
__device__ int   g_batch[NN];
__device__ int   g_is64;
__device__ float g_stats[4];     // two ping-pong slots of (sum, sumsq)

// ---------------- dtype detect: int64 edge_index has zero odd 32-bit words ----------
__global__ void detect_k(const int* __restrict__ ei32, int* __restrict__ flag) {
    __shared__ int nz;
    if (threadIdx.x == 0) nz = 0;
    __syncthreads();
    int v = ei32[threadIdx.x * 2 + 1];
    if (v != 0) atomicAdd(&nz, 1);
    __syncthreads();
    if (threadIdx.x == 0) *flag = (nz == 0) ? 1 : 0;
}

__device__ __forceinline__ int clampN(int v) {
    return v < 0 ? 0 : (v >= NN ? NN - 1 : v);
}

// ---------------- edge prep (convert + degree histogram + batch convert fused) -----
__global__ void convert_hist_k(const int* __restrict__ ei32, const int* __restrict__ flag,
                               int* __restrict__ src, int* __restrict__ dst,
                               int* __restrict__ deg,
                               const int* __restrict__ b32, int* __restrict__ bout) {
    int i = blockIdx.x * blockDim.x + threadIdx.x;
    if (i >= EE) return;
    int f = *flag;
    int s, d;
    if (f) { s = ei32[2 * i];      d = ei32[2 * (EE + i)]; }
    else   { s = ei32[i];          d = ei32[EE + i]; }
    s = clampN(s); d = clampN(d);
    src[i] = s;
    dst[i] = d;
    atomicAdd(&deg[d], 1);
    if (i < NN) {
        int v = f ? b32[2 * i] : b32[i];
        bout[i] = v < 0 ? 0 : (v >= GG ? GG - 1 : v);
    }
}

__global__ void scanA_k(const int* __restrict__ deg, int* __restrict__ incl, int* __restrict__ part) {
    __shared__ int s[1024];
    int i = blockIdx.x * 1024 + threadIdx.x;
    s[threadIdx.x] = (i < NN) ? deg[i] : 0;
    __syncthreads();
    for (int o = 1; o < 1024; o <<= 1) {
        int v = (threadIdx.x >= o) ? s[threadIdx.x - o] : 0;
        __syncthreads();
        s[threadIdx.x] += v;
        __syncthreads();
    }
    if (i < NN) incl[i] = s[threadIdx.x];
    if (threadIdx.x == 1023) part[blockIdx.x] = s[1023];
}

// scanC folds the part-prefix into each block.
__global__ void scanC_k(const int* __restrict__ incl, const int* __restrict__ part,
                        const int* __restrict__ deg, int* __restrict__ off, int* __restrict__ cur) {
    __shared__ int stmp[64];
    __shared__ int sbase;
    int t = threadIdx.x;
    if (t < 64) stmp[t] = (t < blockIdx.x) ? part[t] : 0;
    __syncthreads();
    if (t < 32) {
        int v = stmp[t] + stmp[t + 32];
        #pragma unroll
        for (int o = 16; o >= 1; o >>= 1) v += __shfl_xor_sync(0xffffffffu, v, o);
        if (t == 0) sbase = v;
    }
    __syncthreads();
    int i = blockIdx.x * 1024 + t;
    if (i < NN) {
        int start = incl[i] + sbase - deg[i];
        off[i] = start;
        cur[i] = start;
    }
    if (i == 0) off[NN] = EE;
}

__global__ void scatter_k(const int* __restrict__ src, const int* __restrict__ dst,
                          int* __restrict__ cur, int* __restrict__ csr) {
    int e = blockIdx.x * blockDim.x + threadIdx.x;
    if (e < EE) {
        int d = dst[e];
        int pos = atomicAdd(&cur[d], 1);
        csr[pos] = src[e];
    }
}

// ---------------- tf32 + selu helpers ----------------
__device__ __forceinline__ unsigned f2tf32(float v) {
    unsigned u;
    asm("cvt.rna.tf32.f32 %0, %1;" : "=r"(u) : "f"(v));
    return u;
}

__device__ __forceinline__ float selu_f(float x) {
    const float sc = 1.0507009873554805f, al = 1.6732632423543772f;
    return x > 0.f ? sc * x : sc * al * expm1f(x);
}

// ---------------- tf32 GEMM for layer projections: one block per 128-row chunk ------
// Stages A once (optional fused graph-norm + SELU), loops 8 output-column chunks.
// Block 0 zeroes this layer's stats slot for the following aggregate.
__global__ void __launch_bounds__(256) gemm_tf32_k(
    const float* __restrict__ A,
    const float* __restrict__ W0, const float* __restrict__ W1,
    const float* __restrict__ b0, const float* __restrict__ b1,
    __half* __restrict__ O0, __half* __restrict__ O1, int nrows,
    const float* __restrict__ normstats,
    const float* __restrict__ lw, const float* __restrict__ lb,
    float* __restrict__ zstats)
{
    __shared__ unsigned sA[128 * 68];

    const int t    = threadIdx.x;
    const int lane = t & 31;
    const int grp  = lane >> 2;
    const int qid  = lane & 3;
    const int wid  = t >> 5;
    const int warpM = wid & 3;
    const int warpN = wid >> 2;
    const int mbase = blockIdx.x * 128;

    if (blockIdx.x == 0 && t < 2) zstats[t] = 0.f;

    const int q = t & 15;
    float mean = 0.f, rstd = 1.f;
    float4 w4 = make_float4(1.f, 1.f, 1.f, 1.f), b4 = make_float4(0.f, 0.f, 0.f, 0.f);
    if (normstats) {
        const float invM = 1.f / ((float)NN * 64.f);
        mean = normstats[0] * invM;
        float var = normstats[1] * invM - mean * mean;
        rstd = 1.f / (sqrtf(fmaxf(var, 0.f)) + 1e-5f);
        w4 = *(const float4*)&lw[q * 4];
        b4 = *(const float4*)&lb[q * 4];
    }

    #pragma unroll
    for (int it = 0; it < 8; it++) {
        int idx = it * 256 + t;
        int r = idx >> 4;
        int gr = mbase + r;
        float4 v = make_float4(0.f, 0.f, 0.f, 0.f);
        if (gr < nrows) v = *(const float4*)&A[gr * 64 + q * 4];
        if (normstats) {
            v.x = selu_f((v.x - mean) * rstd * w4.x + b4.x);
            v.y = selu_f((v.y - mean) * rstd * w4.y + b4.y);
            v.z = selu_f((v.z - mean) * rstd * w4.z + b4.z);
            v.w = selu_f((v.w - mean) * rstd * w4.w + b4.w);
        }
        unsigned* dstp = &sA[r * 68 + q * 4];
        dstp[0] = f2tf32(v.x); dstp[1] = f2tf32(v.y);
        dstp[2] = f2tf32(v.z); dstp[3] = f2tf32(v.w);
    }
    __syncthreads();

    #pragma unroll 1
    for (int nc = 0; nc < 8; nc++) {
        const bool half1 = (nc >= 4);
        const float* Wb   = half1 ? W1 : W0;
        const float* bias = half1 ? b1 : b0;
        __half*      Ob   = half1 ? O1 : O0;
        const int nloc = (nc & 3) * 64 + warpN * 32;

        unsigned Breg[8][4][2];
        #pragma unroll
        for (int ks = 0; ks < 8; ks++) {
            #pragma unroll
            for (int nt = 0; nt < 4; nt++) {
                int col = nloc + nt * 8 + grp;
                Breg[ks][nt][0] = f2tf32(Wb[(ks * 8 + qid)     * 256 + col]);
                Breg[ks][nt][1] = f2tf32(Wb[(ks * 8 + qid + 4) * 256 + col]);
            }
        }

        float acc[2][4][4];
        #pragma unroll
        for (int mt = 0; mt < 2; mt++)
            #pragma unroll
            for (int nt = 0; nt < 4; nt++)
                #pragma unroll
                for (int c = 0; c < 4; c++) acc[mt][nt][c] = 0.f;

        #pragma unroll
        for (int ks = 0; ks < 8; ks++) {
            unsigned a[2][4];
            #pragma unroll
            for (int mt = 0; mt < 2; mt++) {
                int r0 = warpM * 32 + mt * 16 + grp;
                int c  = ks * 8 + qid;
                a[mt][0] = sA[r0 * 68 + c];
                a[mt][1] = sA[(r0 + 8) * 68 + c];
                a[mt][2] = sA[r0 * 68 + c + 4];
                a[mt][3] = sA[(r0 + 8) * 68 + c + 4];
            }
            #pragma unroll
            for (int mt = 0; mt < 2; mt++) {
                #pragma unroll
                for (int nt = 0; nt < 4; nt++) {
                    asm volatile(
                        "mma.sync.aligned.m16n8k8.row.col.f32.tf32.tf32.f32 "
                        "{%0,%1,%2,%3}, {%4,%5,%6,%7}, {%8,%9}, {%0,%1,%2,%3};"
                        : "+f"(acc[mt][nt][0]), "+f"(acc[mt][nt][1]),
                          "+f"(acc[mt][nt][2]), "+f"(acc[mt][nt][3])
                        : "r"(a[mt][0]), "r"(a[mt][1]), "r"(a[mt][2]), "r"(a[mt][3]),
                          "r"(Breg[ks][nt][0]), "r"(Breg[ks][nt][1]));
                }
            }
        }

        #pragma unroll
        for (int nt = 0; nt < 4; nt++) {
            int colw = nloc + nt * 8 + qid * 2;
            float bb0 = bias[colw], bb1 = bias[colw + 1];
            #pragma unroll
            for (int mt = 0; mt < 2; mt++) {
                int r0 = mbase + warpM * 32 + mt * 16 + grp;
                if (r0 < nrows)
                    *(__half2*)&Ob[r0 * 256 + colw] =
                        __floats2half2_rn(acc[mt][nt][0] + bb0, acc[mt][nt][1] + bb1);
                int r1 = r0 + 8;
                if (r1 < nrows)
                    *(__half2*)&Ob[r1 * 256 + colw] =
                        __floats2half2_rn(acc[mt][nt][2] + bb0, acc[mt][nt][3] + bb1);
            }
        }
    }
}

// ---------------- tf32 GEMM for initial projection (A[N,128] @ W[128,64]) ----------------
__global__ void __launch_bounds__(256) gemm_tf32_init_k(
    const float* __restrict__ A, const float* __restrict__ W,
    float* __restrict__ O, int nrows)
{
    __shared__ unsigned sA[128 * 68];

    const int t    = threadIdx.x;
    const int lane = t & 31;
    const int wid  = t >> 5;
    const int grp  = lane >> 2;
    const int qid  = lane & 3;
    const int warpM = wid & 3;
    const int warpN = wid >> 2;
    const int nloc = warpN * 32;
    const int mbase = blockIdx.x * 128;

    float acc[2][4][4];
    #pragma unroll
    for (int mt = 0; mt < 2; mt++)
        #pragma unroll
        for (int nt = 0; nt < 4; nt++)
            #pragma unroll
            for (int c = 0; c < 4; c++) acc[mt][nt][c] = 0.f;

    #pragma unroll
    for (int kc = 0; kc < 2; kc++) {
        unsigned Breg[8][4][2];
        #pragma unroll
        for (int ks = 0; ks < 8; ks++) {
            #pragma unroll
            for (int nt = 0; nt < 4; nt++) {
                int col = nloc + nt * 8 + grp;
                int row = kc * 64 + ks * 8;
                Breg[ks][nt][0] = f2tf32(W[(row + qid)     * 64 + col]);
                Breg[ks][nt][1] = f2tf32(W[(row + qid + 4) * 64 + col]);
            }
        }

        #pragma unroll
        for (int it = 0; it < 8; it++) {
            int idx = it * 256 + t;
            int r = idx >> 4, q = idx & 15;
            int gr = mbase + r;
            float4 v = make_float4(0.f, 0.f, 0.f, 0.f);
            if (gr < nrows) v = *(const float4*)&A[gr * 128 + kc * 64 + q * 4];
            unsigned* dstp = &sA[r * 68 + q * 4];
            dstp[0] = f2tf32(v.x); dstp[1] = f2tf32(v.y);
            dstp[2] = f2tf32(v.z); dstp[3] = f2tf32(v.w);
        }
        __syncthreads();

        #pragma unroll
        for (int ks = 0; ks < 8; ks++) {
            unsigned a[2][4];
            #pragma unroll
            for (int mt = 0; mt < 2; mt++) {
                int r0 = warpM * 32 + mt * 16 + grp;
                int c  = ks * 8 + qid;
                a[mt][0] = sA[r0 * 68 + c];
                a[mt][1] = sA[(r0 + 8) * 68 + c];
                a[mt][2] = sA[r0 * 68 + c + 4];
                a[mt][3] = sA[(r0 + 8) * 68 + c + 4];
            }
            #pragma unroll
            for (int mt = 0; mt < 2; mt++) {
                #pragma unroll
                for (int nt = 0; nt < 4; nt++) {
                    asm volatile(
                        "mma.sync.aligned.m16n8k8.row.col.f32.tf32.tf32.f32 "
                        "{%0,%1,%2,%3}, {%4,%5,%6,%7}, {%8,%9}, {%0,%1,%2,%3};"
                        : "+f"(acc[mt][nt][0]), "+f"(acc[mt][nt][1]),
                          "+f"(acc[mt][nt][2]), "+f"(acc[mt][nt][3])
                        : "r"(a[mt][0]), "r"(a[mt][1]), "r"(a[mt][2]), "r"(a[mt][3]),
                          "r"(Breg[ks][nt][0]), "r"(Breg[ks][nt][1]));
                }
            }
        }
        __syncthreads();
    }

    #pragma unroll
    for (int nt = 0; nt < 4; nt++) {
        int colw = nloc + nt * 8 + qid * 2;
        #pragma unroll
        for (int mt = 0; mt < 2; mt++) {
            int r0 = mbase + warpM * 32 + mt * 16 + grp;
            if (r0 < nrows)
                *(float2*)&O[r0 * 64 + colw] = make_float2(acc[mt][nt][0], acc[mt][nt][1]);
            int r1 = r0 + 8;
            if (r1 < nrows)
                *(float2*)&O[r1 * 64 + colw] = make_float2(acc[mt][nt][2], acc[mt][nt][3]);
        }
    }
}

// ---------------- GATv2 aggregate: 8 warps/block (Round-10 proven config) ----------
__global__ void __launch_bounds__(256) aggregate_k(
    const __half* __restrict__ xl, const __half* __restrict__ xr,
    const int* __restrict__ off, const int* __restrict__ csr,
    const float* __restrict__ att, const float* __restrict__ cb,
    float* __restrict__ hn, float* __restrict__ stats)
{
    int warp = threadIdx.x >> 5, lane = threadIdx.x & 31;
    int i = blockIdx.x * 8 + warp;
    __shared__ float ssum[2];
    if (threadIdx.x < 2) ssum[threadIdx.x] = 0.f;
    __syncthreads();

    if (i < NN) {
        const float4* xl4 = (const float4*)xl;
        const float4* xr4 = (const float4*)xr;
        __half2 rr2[4];
        {
            float4 rv = xr4[i * 32 + lane];
            const __half2* hp = (const __half2*)&rv;
            #pragma unroll
            for (int k = 0; k < 4; k++) rr2[k] = hp[k];
        }
        int head = lane >> 3, cg = lane & 7;
        __half2 att2[4];
        #pragma unroll
        for (int k = 0; k < 4; k++)
            att2[k] = __floats2half2_rn(att[head * 64 + cg * 8 + 2 * k],
                                        att[head * 64 + cg * 8 + 2 * k + 1]);
        const __half2 c02 = __float2half2_rn(0.2f);

        float d = 0.f;
        __half2 acc2[4];
        #pragma unroll
        for (int k = 0; k < 4; k++) acc2[k] = __float2half2_rn(0.f);
        int e0 = off[i], e1 = off[i + 1];

        float4 sa, sb;
        if (e0 < e1)     sa = xl4[csr[e0] * 32 + lane];
        if (e0 + 1 < e1) sb = xl4[csr[e0 + 1] * 32 + lane];
        for (int e = e0; e < e1; e++) {
            float4 cur = sa;
            sa = sb;
            if (e + 2 < e1) sb = xl4[csr[e + 2] * 32 + lane];

            const __half2* x2 = (const __half2*)&cur;
            __half2 p2 = __float2half2_rn(0.f);
            #pragma unroll
            for (int k = 0; k < 4; k++) {
                __half2 v2 = __hadd2(x2[k], rr2[k]);
                __half2 lv = __hmax2(v2, __hmul2(v2, c02));
                p2 = __hfma2(lv, att2[k], p2);
            }
            float2 pf = __half22float2(p2);
            float p = pf.x + pf.y;
            p += __shfl_xor_sync(0xffffffffu, p, 4);
            p += __shfl_xor_sync(0xffffffffu, p, 2);
            p += __shfl_xor_sync(0xffffffffu, p, 1);
            float w = __expf(fminf(p, 60.f));
            d += w;
            __half2 w2 = __float2half2_rn(w);
            #pragma unroll
            for (int k = 0; k < 4; k++) acc2[k] = __hfma2(w2, x2[k], acc2[k]);
        }
        float inv = (d > 0.f) ? 1.f / d : 0.f;
        float o[8];
        #pragma unroll
        for (int k = 0; k < 4; k++) {
            float2 f = __half22float2(acc2[k]);
            o[2 * k]     = f.x * inv;
            o[2 * k + 1] = f.y * inv;
        }
        #pragma unroll
        for (int j = 0; j < 8; j++) o[j] += __shfl_xor_sync(0xffffffffu, o[j], 8);
        #pragma unroll
        for (int j = 0; j < 8; j++) o[j] += __shfl_xor_sync(0xffffffffu, o[j], 16);
        float ls = 0.f, lq = 0.f;
        #pragma unroll
        for (int j = 0; j < 8; j++) {
            o[j] = o[j] * 0.25f + cb[cg * 8 + j];
            ls += o[j];
            lq += o[j] * o[j];
        }
        if (lane < 8) {
            float4* hn4 = (float4*)hn;
            hn4[i * 16 + lane * 2]     = make_float4(o[0], o[1], o[2], o[3]);
            hn4[i * 16 + lane * 2 + 1] = make_float4(o[4], o[5], o[6], o[7]);
        }
        #pragma unroll
        for (int ofs = 16; ofs >= 1; ofs >>= 1) {
            ls += __shfl_xor_sync(0xffffffffu, ls, ofs);
            lq += __shfl_xor_sync(0xffffffffu, lq, ofs);
        }
        if (lane == 0) {
            atomicAdd(&ssum[0], ls * 0.25f);
            atomicAdd(&ssum[1], lq * 0.25f);
        }
    }
    __syncthreads();
    if (threadIdx.x == 0) {
        atomicAdd(&stats[0], ssum[0]);
        atomicAdd(&stats[1], ssum[1]);
    }
}

// ---------------- mean pool per graph (fused final norm+SELU, pipelined loads) ------
__device__ __forceinline__ int lbound_i(const int* a, int n, int key) {
    int lo = 0, hi = n;
    while (lo < hi) {
        int m = (lo + hi) >> 1;
        if (a[m] < key) lo = m + 1; else hi = m;
    }
    return lo;
}

__global__ void pool_k(const float* __restrict__ hn, const float* __restrict__ stats,
                       const float* __restrict__ lw, const float* __restrict__ lb,
                       const int* __restrict__ batch,
                       const float* __restrict__ Wh, const float* __restrict__ bh,
                       float* __restrict__ out)
{
    int g = blockIdx.x;
    __shared__ int slo, shi;
    __shared__ float sacc[4][64];
    __shared__ float sdot[64];
    int t = threadIdx.x;
    if (t == 0) {
        slo = lbound_i(batch, NN, g);
        shi = lbound_i(batch, NN, g + 1);
    }
    __syncthreads();
    const float invM = 1.f / ((float)NN * 64.f);
    float mean = stats[0] * invM;
    float var  = stats[1] * invM - mean * mean;
    float rstd = 1.f / (sqrtf(fmaxf(var, 0.f)) + 1e-5f);
    int lo = slo, hi = shi;
    int c = t & 63, slot = t >> 6;
    float wc = lw[c] * rstd, bc = lb[c] - mean * rstd * lw[c];
    float p = 0.f;
    // Batch 4 loads into registers BEFORE the selu chain — keeps MLP=4 even though
    // selu's expm1f control flow would otherwise serialize the loop at L2 latency.
    int n = lo + slot;
    for (; n + 12 < hi; n += 16) {
        float v0 = hn[n * 64 + c];
        float v1 = hn[(n + 4) * 64 + c];
        float v2 = hn[(n + 8) * 64 + c];
        float v3 = hn[(n + 12) * 64 + c];
        p += selu_f(v0 * wc + bc);
        p += selu_f(v1 * wc + bc);
        p += selu_f(v2 * wc + bc);
        p += selu_f(v3 * wc + bc);
    }
    for (; n < hi; n += 4)
        p += selu_f(hn[n * 64 + c] * wc + bc);
    sacc[slot][c] = p;
    __syncthreads();
    if (slot == 0) {
        float tot = sacc[0][c] + sacc[1][c] + sacc[2][c] + sacc[3][c];
        float cnt = (float)((hi - lo) > 1 ? (hi - lo) : 1);
        sdot[c] = (tot / cnt) * Wh[c];
    }
    __syncthreads();
    if (t < 32) {
        float v = sdot[t] + sdot[t + 32];
        #pragma unroll
        for (int o = 16; o >= 1; o >>= 1) v += __shfl_xor_sync(0xffffffffu, v, o);
        if (t == 0) out[g] = v + bh[0];
    }
}

// ---------------- launch ----------------
extern "C" void kernel_launch(void* const* d_in, const int* in_sizes, int n_in,
                              void* d_out, int out_size)
{
    const float* x     = (const float*)d_in[0];
    const int*   ei32  = (const int*)d_in[1];   // int32 or int64 (auto-detected)
    const int*   b32   = (const int*)d_in[2];
    const float* Wp    = (const float*)d_in[3];
    const float* Wl    = (const float*)d_in[4];
    const float* bl    = (const float*)d_in[5];
    const float* Wr    = (const float*)d_in[6];
    const float* br    = (const float*)d_in[7];
    const float* att   = (const float*)d_in[8];
    const float* cb    = (const float*)d_in[9];
    const float* lnw   = (const float*)d_in[10];
    const float* lnb   = (const float*)d_in[11];
    const float* Wh    = (const float*)d_in[12];
    const float* bh    = (const float*)d_in[13];
    float* out = (float*)d_out;

    float *p_h, *p_hn, *p_stats;
    __half *p_xl, *p_xr;
    int *p_src, *p_dst, *p_csr, *p_deg, *p_incl, *p_off, *p_cur, *p_part, *p_batch, *p_flag;
    cudaGetSymbolAddress((void**)&p_h,    g_h);
    cudaGetSymbolAddress((void**)&p_hn,   g_hn);
    cudaGetSymbolAddress((void**)&p_xl,   g_xl);
    cudaGetSymbolAddress((void**)&p_xr,   g_xr);
    cudaGetSymbolAddress((void**)&p_stats,g_stats);
    cudaGetSymbolAddress((void**)&p_src,  g_src);
    cudaGetSymbolAddress((void**)&p_dst,  g_dst);
    cudaGetSymbolAddress((void**)&p_csr,  g_csr);
    cudaGetSymbolAddress((void**)&p_deg,  g_deg);
    cudaGetSymbolAddress((void**)&p_incl, g_incl);
    cudaGetSymbolAddress((void**)&p_off,  g_off);
    cudaGetSymbolAddress((void**)&p_cur,  g_cur);
    cudaGetSymbolAddress((void**)&p_part, g_part);
    cudaGetSymbolAddress((void**)&p_batch,g_batch);
    cudaGetSymbolAddress((void**)&p_flag, g_is64);

    // dtype detect + CSR build (per call; edge_index is an input)
    detect_k<<<1, 256>>>(ei32, p_flag);
    cudaMemsetAsync(p_deg, 0, NN * sizeof(int));
    convert_hist_k<<<(EE + 255) / 256, 256>>>(ei32, p_flag, p_src, p_dst, p_deg, b32, p_batch);
    scanA_k<<<NB, 1024>>>(p_deg, p_incl, p_part);
    scanC_k<<<NB, 1024>>>(p_incl, p_part, p_deg, p_off, p_cur);
    scatter_k<<<(EE + 255) / 256, 256>>>(p_src, p_dst, p_cur, p_csr);

    // initial projection: h = x @ Wp (tf32 tensor cores)
    gemm_tf32_init_k<<<(NN + 127) / 128, 256>>>(x, Wp, p_h, NN);

    const int NCHUNK = (NN + 127) / 128;
    for (int l = 0; l < LL; l++) {
        float* slotCur  = p_stats + (l & 1) * 2;
        const float* slotPrev = p_stats + ((l + 1) & 1) * 2;
        const float* Ain = (l == 0) ? p_h : p_hn;
        gemm_tf32_k<<<NCHUNK, 256>>>(
            Ain, Wl + l * 64 * 256, Wr + l * 64 * 256,
            bl + l * 256, br + l * 256, p_xl, p_xr, NN,
            (l == 0) ? nullptr : slotPrev,
            (l == 0) ? nullptr : (lnw + (l - 1) * CC),
            (l == 0) ? nullptr : (lnb + (l - 1) * CC),
            slotCur);
        aggregate_k<<<(NN + 7) / 8, 256>>>(p_xl, p_xr, p_off, p_csr,
                                           att + l * HH * CC, cb + l * CC, p_hn, slotCur);
    }

    // pool with fused final graph-norm + SELU (pipelined loads)
    pool_k<<<GG, 256>>>(p_hn, p_stats + ((LL - 1) & 1) * 2,
                        lnw + (LL - 1) * CC, lnb + (LL - 1) * CC,
                        p_batch, Wh, bh, out);
}

// round 14
// speedup vs baseline: 1.1722x; 1.0775x over previous
#include <cuda_runtime.h>
#include <cuda_fp16.h>
#include <math.h>

#define NN 50000
#define FF 128
#define CC 64
#define HH 4
#define EE 500000
#define GG 32
#define LL 4
#define NB 49   // scan blocks = ceil(NN/1024)

// ---------------- scratch (static device globals; no allocation allowed) ----------
__device__ __align__(16) float  g_h [NN*CC];
__device__ __align__(16) float  g_hn[NN*CC];
__device__ __align__(16) __half g_xl[NN*HH*CC];
__device__ __align__(16) __half g_xr[NN*HH*CC];
__device__ int   g_src[EE];
__device__ int   g_dst[EE];
__device__ int   g_csr[EE];
__device__ int   g_deg[NN];
__device__ int   g_incl[NN];
__device__ int   g_off[NN+1];
__device__ int   g_cur[NN];
__device__ int   g_part[64];
__device__ int   g_batch[NN];
__device__ int   g_is64;
__device__ float g_stats[4];     // two ping-pong slots of (sum, sumsq)

// ---------------- dtype detect: int64 edge_index has zero odd 32-bit words ----------
__global__ void detect_k(const int* __restrict__ ei32, int* __restrict__ flag) {
    __shared__ int nz;
    if (threadIdx.x == 0) nz = 0;
    __syncthreads();
    int v = ei32[threadIdx.x * 2 + 1];
    if (v != 0) atomicAdd(&nz, 1);
    __syncthreads();
    if (threadIdx.x == 0) *flag = (nz == 0) ? 1 : 0;
}

__device__ __forceinline__ int clampN(int v) {
    return v < 0 ? 0 : (v >= NN ? NN - 1 : v);
}

// ---------------- edge prep (convert + degree histogram + batch convert fused) -----
__global__ void convert_hist_k(const int* __restrict__ ei32, const int* __restrict__ flag,
                               int* __restrict__ src, int* __restrict__ dst,
                               int* __restrict__ deg,
                               const int* __restrict__ b32, int* __restrict__ bout) {
    int i = blockIdx.x * blockDim.x + threadIdx.x;
    if (i >= EE) return;
    int f = *flag;
    int s, d;
    if (f) { s = ei32[2 * i];      d = ei32[2 * (EE + i)]; }
    else   { s = ei32[i];          d = ei32[EE + i]; }
    s = clampN(s); d = clampN(d);
    src[i] = s;
    dst[i] = d;
    atomicAdd(&deg[d], 1);
    if (i < NN) {
        int v = f ? b32[2 * i] : b32[i];
        bout[i] = v < 0 ? 0 : (v >= GG ? GG - 1 : v);
    }
}

__global__ void scanA_k(const int* __restrict__ deg, int* __restrict__ incl, int* __restrict__ part) {
    __shared__ int s[1024];
    int i = blockIdx.x * 1024 + threadIdx.x;
    s[threadIdx.x] = (i < NN) ? deg[i] : 0;
    __syncthreads();
    for (int o = 1; o < 1024; o <<= 1) {
        int v = (threadIdx.x >= o) ? s[threadIdx.x - o] : 0;
        __syncthreads();
        s[threadIdx.x] += v;
        __syncthreads();
    }
    if (i < NN) incl[i] = s[threadIdx.x];
    if (threadIdx.x == 1023) part[blockIdx.x] = s[1023];
}

// scanC folds the part-prefix into each block.
__global__ void scanC_k(const int* __restrict__ incl, const int* __restrict__ part,
                        const int* __restrict__ deg, int* __restrict__ off, int* __restrict__ cur) {
    __shared__ int stmp[64];
    __shared__ int sbase;
    int t = threadIdx.x;
    if (t < 64) stmp[t] = (t < blockIdx.x) ? part[t] : 0;
    __syncthreads();
    if (t < 32) {
        int v = stmp[t] + stmp[t + 32];
        #pragma unroll
        for (int o = 16; o >= 1; o >>= 1) v += __shfl_xor_sync(0xffffffffu, v, o);
        if (t == 0) sbase = v;
    }
    __syncthreads();
    int i = blockIdx.x * 1024 + t;
    if (i < NN) {
        int start = incl[i] + sbase - deg[i];
        off[i] = start;
        cur[i] = start;
    }
    if (i == 0) off[NN] = EE;
}

__global__ void scatter_k(const int* __restrict__ src, const int* __restrict__ dst,
                          int* __restrict__ cur, int* __restrict__ csr) {
    int e = blockIdx.x * blockDim.x + threadIdx.x;
    if (e < EE) {
        int d = dst[e];
        int pos = atomicAdd(&cur[d], 1);
        csr[pos] = src[e];
    }
}

// ---------------- tf32 + selu helpers ----------------
__device__ __forceinline__ unsigned f2tf32(float v) {
    unsigned u;
    asm("cvt.rna.tf32.f32 %0, %1;" : "=r"(u) : "f"(v));
    return u;
}

__device__ __forceinline__ float selu_f(float x) {
    const float sc = 1.0507009873554805f, al = 1.6732632423543772f;
    return x > 0.f ? sc * x : sc * al * expm1f(x);
}

// ---------------- tf32 GEMM for layer projections: one block per 128-row chunk ------
// Stages A once (optional fused graph-norm + SELU), loops 8 output-column chunks.
// Block 0 zeroes this layer's stats slot for the following aggregate.
__global__ void __launch_bounds__(256) gemm_tf32_k(
    const float* __restrict__ A,
    const float* __restrict__ W0, const float* __restrict__ W1,
    const float* __restrict__ b0, const float* __restrict__ b1,
    __half* __restrict__ O0, __half* __restrict__ O1, int nrows,
    const float* __restrict__ normstats,
    const float* __restrict__ lw, const float* __restrict__ lb,
    float* __restrict__ zstats)
{
    __shared__ unsigned sA[128 * 68];

    const int t    = threadIdx.x;
    const int lane = t & 31;
    const int grp  = lane >> 2;
    const int qid  = lane & 3;
    const int wid  = t >> 5;
    const int warpM = wid & 3;
    const int warpN = wid >> 2;
    const int mbase = blockIdx.x * 128;

    if (blockIdx.x == 0 && t < 2) zstats[t] = 0.f;

    const int q = t & 15;
    float mean = 0.f, rstd = 1.f;
    float4 w4 = make_float4(1.f, 1.f, 1.f, 1.f), b4 = make_float4(0.f, 0.f, 0.f, 0.f);
    if (normstats) {
        const float invM = 1.f / ((float)NN * 64.f);
        mean = normstats[0] * invM;
        float var = normstats[1] * invM - mean * mean;
        rstd = 1.f / (sqrtf(fmaxf(var, 0.f)) + 1e-5f);
        w4 = *(const float4*)&lw[q * 4];
        b4 = *(const float4*)&lb[q * 4];
    }

    #pragma unroll
    for (int it = 0; it < 8; it++) {
        int idx = it * 256 + t;
        int r = idx >> 4;
        int gr = mbase + r;
        float4 v = make_float4(0.f, 0.f, 0.f, 0.f);
        if (gr < nrows) v = *(const float4*)&A[gr * 64 + q * 4];
        if (normstats) {
            v.x = selu_f((v.x - mean) * rstd * w4.x + b4.x);
            v.y = selu_f((v.y - mean) * rstd * w4.y + b4.y);
            v.z = selu_f((v.z - mean) * rstd * w4.z + b4.z);
            v.w = selu_f((v.w - mean) * rstd * w4.w + b4.w);
        }
        unsigned* dstp = &sA[r * 68 + q * 4];
        dstp[0] = f2tf32(v.x); dstp[1] = f2tf32(v.y);
        dstp[2] = f2tf32(v.z); dstp[3] = f2tf32(v.w);
    }
    __syncthreads();

    #pragma unroll 1
    for (int nc = 0; nc < 8; nc++) {
        const bool half1 = (nc >= 4);
        const float* Wb   = half1 ? W1 : W0;
        const float* bias = half1 ? b1 : b0;
        __half*      Ob   = half1 ? O1 : O0;
        const int nloc = (nc & 3) * 64 + warpN * 32;

        unsigned Breg[8][4][2];
        #pragma unroll
        for (int ks = 0; ks < 8; ks++) {
            #pragma unroll
            for (int nt = 0; nt < 4; nt++) {
                int col = nloc + nt * 8 + grp;
                Breg[ks][nt][0] = f2tf32(Wb[(ks * 8 + qid)     * 256 + col]);
                Breg[ks][nt][1] = f2tf32(Wb[(ks * 8 + qid + 4) * 256 + col]);
            }
        }

        float acc[2][4][4];
        #pragma unroll
        for (int mt = 0; mt < 2; mt++)
            #pragma unroll
            for (int nt = 0; nt < 4; nt++)
                #pragma unroll
                for (int c = 0; c < 4; c++) acc[mt][nt][c] = 0.f;

        #pragma unroll
        for (int ks = 0; ks < 8; ks++) {
            unsigned a[2][4];
            #pragma unroll
            for (int mt = 0; mt < 2; mt++) {
                int r0 = warpM * 32 + mt * 16 + grp;
                int c  = ks * 8 + qid;
                a[mt][0] = sA[r0 * 68 + c];
                a[mt][1] = sA[(r0 + 8) * 68 + c];
                a[mt][2] = sA[r0 * 68 + c + 4];
                a[mt][3] = sA[(r0 + 8) * 68 + c + 4];
            }
            #pragma unroll
            for (int mt = 0; mt < 2; mt++) {
                #pragma unroll
                for (int nt = 0; nt < 4; nt++) {
                    asm volatile(
                        "mma.sync.aligned.m16n8k8.row.col.f32.tf32.tf32.f32 "
                        "{%0,%1,%2,%3}, {%4,%5,%6,%7}, {%8,%9}, {%0,%1,%2,%3};"
                        : "+f"(acc[mt][nt][0]), "+f"(acc[mt][nt][1]),
                          "+f"(acc[mt][nt][2]), "+f"(acc[mt][nt][3])
                        : "r"(a[mt][0]), "r"(a[mt][1]), "r"(a[mt][2]), "r"(a[mt][3]),
                          "r"(Breg[ks][nt][0]), "r"(Breg[ks][nt][1]));
                }
            }
        }

        #pragma unroll
        for (int nt = 0; nt < 4; nt++) {
            int colw = nloc + nt * 8 + qid * 2;
            float bb0 = bias[colw], bb1 = bias[colw + 1];
            #pragma unroll
            for (int mt = 0; mt < 2; mt++) {
                int r0 = mbase + warpM * 32 + mt * 16 + grp;
                if (r0 < nrows)
                    *(__half2*)&Ob[r0 * 256 + colw] =
                        __floats2half2_rn(acc[mt][nt][0] + bb0, acc[mt][nt][1] + bb1);
                int r1 = r0 + 8;
                if (r1 < nrows)
                    *(__half2*)&Ob[r1 * 256 + colw] =
                        __floats2half2_rn(acc[mt][nt][2] + bb0, acc[mt][nt][3] + bb1);
            }
        }
    }
}

// ---------------- tf32 GEMM for initial projection (A[N,128] @ W[128,64]) ----------------
__global__ void __launch_bounds__(256) gemm_tf32_init_k(
    const float* __restrict__ A, const float* __restrict__ W,
    float* __restrict__ O, int nrows)
{
    __shared__ unsigned sA[128 * 68];

    const int t    = threadIdx.x;
    const int lane = t & 31;
    const int wid  = t >> 5;
    const int grp  = lane >> 2;
    const int qid  = lane & 3;
    const int warpM = wid & 3;
    const int warpN = wid >> 2;
    const int nloc = warpN * 32;
    const int mbase = blockIdx.x * 128;

    float acc[2][4][4];
    #pragma unroll
    for (int mt = 0; mt < 2; mt++)
        #pragma unroll
        for (int nt = 0; nt < 4; nt++)
            #pragma unroll
            for (int c = 0; c < 4; c++) acc[mt][nt][c] = 0.f;

    #pragma unroll
    for (int kc = 0; kc < 2; kc++) {
        unsigned Breg[8][4][2];
        #pragma unroll
        for (int ks = 0; ks < 8; ks++) {
            #pragma unroll
            for (int nt = 0; nt < 4; nt++) {
                int col = nloc + nt * 8 + grp;
                int row = kc * 64 + ks * 8;
                Breg[ks][nt][0] = f2tf32(W[(row + qid)     * 64 + col]);
                Breg[ks][nt][1] = f2tf32(W[(row + qid + 4) * 64 + col]);
            }
        }

        #pragma unroll
        for (int it = 0; it < 8; it++) {
            int idx = it * 256 + t;
            int r = idx >> 4, q = idx & 15;
            int gr = mbase + r;
            float4 v = make_float4(0.f, 0.f, 0.f, 0.f);
            if (gr < nrows) v = *(const float4*)&A[gr * 128 + kc * 64 + q * 4];
            unsigned* dstp = &sA[r * 68 + q * 4];
            dstp[0] = f2tf32(v.x); dstp[1] = f2tf32(v.y);
            dstp[2] = f2tf32(v.z); dstp[3] = f2tf32(v.w);
        }
        __syncthreads();

        #pragma unroll
        for (int ks = 0; ks < 8; ks++) {
            unsigned a[2][4];
            #pragma unroll
            for (int mt = 0; mt < 2; mt++) {
                int r0 = warpM * 32 + mt * 16 + grp;
                int c  = ks * 8 + qid;
                a[mt][0] = sA[r0 * 68 + c];
                a[mt][1] = sA[(r0 + 8) * 68 + c];
                a[mt][2] = sA[r0 * 68 + c + 4];
                a[mt][3] = sA[(r0 + 8) * 68 + c + 4];
            }
            #pragma unroll
            for (int mt = 0; mt < 2; mt++) {
                #pragma unroll
                for (int nt = 0; nt < 4; nt++) {
                    asm volatile(
                        "mma.sync.aligned.m16n8k8.row.col.f32.tf32.tf32.f32 "
                        "{%0,%1,%2,%3}, {%4,%5,%6,%7}, {%8,%9}, {%0,%1,%2,%3};"
                        : "+f"(acc[mt][nt][0]), "+f"(acc[mt][nt][1]),
                          "+f"(acc[mt][nt][2]), "+f"(acc[mt][nt][3])
                        : "r"(a[mt][0]), "r"(a[mt][1]), "r"(a[mt][2]), "r"(a[mt][3]),
                          "r"(Breg[ks][nt][0]), "r"(Breg[ks][nt][1]));
                }
            }
        }
        __syncthreads();
    }

    #pragma unroll
    for (int nt = 0; nt < 4; nt++) {
        int colw = nloc + nt * 8 + qid * 2;
        #pragma unroll
        for (int mt = 0; mt < 2; mt++) {
            int r0 = mbase + warpM * 32 + mt * 16 + grp;
            if (r0 < nrows)
                *(float2*)&O[r0 * 64 + colw] = make_float2(acc[mt][nt][0], acc[mt][nt][1]);
            int r1 = r0 + 8;
            if (r1 < nrows)
                *(float2*)&O[r1 * 64 + colw] = make_float2(acc[mt][nt][2], acc[mt][nt][3]);
        }
    }
}

// ---------------- GATv2 aggregate: 8 warps/block, fp16 feats, half2 math -----------
__global__ void __launch_bounds__(256) aggregate_k(
    const __half* __restrict__ xl, const __half* __restrict__ xr,
    const int* __restrict__ off, const int* __restrict__ csr,
    const float* __restrict__ att, const float* __restrict__ cb,
    float* __restrict__ hn, float* __restrict__ stats)
{
    int warp = threadIdx.x >> 5, lane = threadIdx.x & 31;
    int i = blockIdx.x * 8 + warp;
    __shared__ float ssum[2];
    if (threadIdx.x < 2) ssum[threadIdx.x] = 0.f;
    __syncthreads();

    if (i < NN) {
        const float4* xl4 = (const float4*)xl;
        const float4* xr4 = (const float4*)xr;
        __half2 rr2[4];
        {
            float4 rv = xr4[i * 32 + lane];
            const __half2* hp = (const __half2*)&rv;
            #pragma unroll
            for (int k = 0; k < 4; k++) rr2[k] = hp[k];
        }
        int head = lane >> 3, cg = lane & 7;
        __half2 att2[4];
        #pragma unroll
        for (int k = 0; k < 4; k++)
            att2[k] = __floats2half2_rn(att[head * 64 + cg * 8 + 2 * k],
                                        att[head * 64 + cg * 8 + 2 * k + 1]);
        const __half2 c02 = __float2half2_rn(0.2f);

        float d = 0.f;
        __half2 acc2[4];
        #pragma unroll
        for (int k = 0; k < 4; k++) acc2[k] = __float2half2_rn(0.f);
        int e0 = off[i], e1 = off[i + 1];

        float4 sa, sb;
        if (e0 < e1)     sa = xl4[csr[e0] * 32 + lane];
        if (e0 + 1 < e1) sb = xl4[csr[e0 + 1] * 32 + lane];
        for (int e = e0; e < e1; e++) {
            float4 cur = sa;
            sa = sb;
            if (e + 2 < e1) sb = xl4[csr[e + 2] * 32 + lane];

            const __half2* x2 = (const __half2*)&cur;
            __half2 p2 = __float2half2_rn(0.f);
            #pragma unroll
            for (int k = 0; k < 4; k++) {
                __half2 v2 = __hadd2(x2[k], rr2[k]);
                __half2 lv = __hmax2(v2, __hmul2(v2, c02));
                p2 = __hfma2(lv, att2[k], p2);
            }
            float2 pf = __half22float2(p2);
            float p = pf.x + pf.y;
            p += __shfl_xor_sync(0xffffffffu, p, 4);
            p += __shfl_xor_sync(0xffffffffu, p, 2);
            p += __shfl_xor_sync(0xffffffffu, p, 1);
            float w = __expf(fminf(p, 60.f));
            d += w;
            __half2 w2 = __float2half2_rn(w);
            #pragma unroll
            for (int k = 0; k < 4; k++) acc2[k] = __hfma2(w2, x2[k], acc2[k]);
        }
        float inv = (d > 0.f) ? 1.f / d : 0.f;
        float o[8];
        #pragma unroll
        for (int k = 0; k < 4; k++) {
            float2 f = __half22float2(acc2[k]);
            o[2 * k]     = f.x * inv;
            o[2 * k + 1] = f.y * inv;
        }
        #pragma unroll
        for (int j = 0; j < 8; j++) o[j] += __shfl_xor_sync(0xffffffffu, o[j], 8);
        #pragma unroll
        for (int j = 0; j < 8; j++) o[j] += __shfl_xor_sync(0xffffffffu, o[j], 16);
        float ls = 0.f, lq = 0.f;
        #pragma unroll
        for (int j = 0; j < 8; j++) {
            o[j] = o[j] * 0.25f + cb[cg * 8 + j];
            ls += o[j];
            lq += o[j] * o[j];
        }
        if (lane < 8) {
            float4* hn4 = (float4*)hn;
            hn4[i * 16 + lane * 2]     = make_float4(o[0], o[1], o[2], o[3]);
            hn4[i * 16 + lane * 2 + 1] = make_float4(o[4], o[5], o[6], o[7]);
        }
        #pragma unroll
        for (int ofs = 16; ofs >= 1; ofs >>= 1) {
            ls += __shfl_xor_sync(0xffffffffu, ls, ofs);
            lq += __shfl_xor_sync(0xffffffffu, lq, ofs);
        }
        if (lane == 0) {
            atomicAdd(&ssum[0], ls * 0.25f);
            atomicAdd(&ssum[1], lq * 0.25f);
        }
    }
    __syncthreads();
    if (threadIdx.x == 0) {
        atomicAdd(&stats[0], ssum[0]);
        atomicAdd(&stats[1], ssum[1]);
    }
}

// ---------------- global graph-norm + SELU (after final layer only) ----------------
__global__ void norm_k(const float4* __restrict__ hn, const float* __restrict__ stats,
                       const float* __restrict__ w, const float* __restrict__ b,
                       float4* __restrict__ h)
{
    int idx = blockIdx.x * blockDim.x + threadIdx.x;
    if (idx >= NN * 16) return;
    const float invM = 1.f / ((float)NN * 64.f);
    float mean = stats[0] * invM;
    float var  = stats[1] * invM - mean * mean;
    float rstd = 1.f / (sqrtf(fmaxf(var, 0.f)) + 1e-5f);
    int c = (idx * 4) & 63;
    float4 v = hn[idx];
    v.x = selu_f((v.x - mean) * rstd * w[c + 0] + b[c + 0]);
    v.y = selu_f((v.y - mean) * rstd * w[c + 1] + b[c + 1]);
    v.z = selu_f((v.z - mean) * rstd * w[c + 2] + b[c + 2]);
    v.w = selu_f((v.w - mean) * rstd * w[c + 3] + b[c + 3]);
    h[idx] = v;
}

// ---------------- mean pool per graph + head projection ----------------
__device__ __forceinline__ int lbound_i(const int* a, int n, int key) {
    int lo = 0, hi = n;
    while (lo < hi) {
        int m = (lo + hi) >> 1;
        if (a[m] < key) lo = m + 1; else hi = m;
    }
    return lo;
}

__global__ void pool_k(const float* __restrict__ h, const int* __restrict__ batch,
                       const float* __restrict__ Wh, const float* __restrict__ bh,
                       float* __restrict__ out)
{
    int g = blockIdx.x;
    __shared__ int slo, shi;
    __shared__ float sacc[4][64];
    __shared__ float sdot[64];
    int t = threadIdx.x;
    if (t == 0) {
        slo = lbound_i(batch, NN, g);
        shi = lbound_i(batch, NN, g + 1);
    }
    __syncthreads();
    int lo = slo, hi = shi;
    int c = t & 63, slot = t >> 6;
    float p = 0.f;
    for (int n = lo + slot; n < hi; n += 4) p += h[n * 64 + c];
    sacc[slot][c] = p;
    __syncthreads();
    if (slot == 0) {
        float tot = sacc[0][c] + sacc[1][c] + sacc[2][c] + sacc[3][c];
        float cnt = (float)((hi - lo) > 1 ? (hi - lo) : 1);
        sdot[c] = (tot / cnt) * Wh[c];
    }
    __syncthreads();
    if (t < 32) {
        float v = sdot[t] + sdot[t + 32];
        #pragma unroll
        for (int o = 16; o >= 1; o >>= 1) v += __shfl_xor_sync(0xffffffffu, v, o);
        if (t == 0) out[g] = v + bh[0];
    }
}

// ---------------- launch ----------------
extern "C" void kernel_launch(void* const* d_in, const int* in_sizes, int n_in,
                              void* d_out, int out_size)
{
    const float* x     = (const float*)d_in[0];
    const int*   ei32  = (const int*)d_in[1];   // int32 or int64 (auto-detected)
    const int*   b32   = (const int*)d_in[2];
    const float* Wp    = (const float*)d_in[3];
    const float* Wl    = (const float*)d_in[4];
    const float* bl    = (const float*)d_in[5];
    const float* Wr    = (const float*)d_in[6];
    const float* br    = (const float*)d_in[7];
    const float* att   = (const float*)d_in[8];
    const float* cb    = (const float*)d_in[9];
    const float* lnw   = (const float*)d_in[10];
    const float* lnb   = (const float*)d_in[11];
    const float* Wh    = (const float*)d_in[12];
    const float* bh    = (const float*)d_in[13];
    float* out = (float*)d_out;

    float *p_h, *p_hn, *p_stats;
    __half *p_xl, *p_xr;
    int *p_src, *p_dst, *p_csr, *p_deg, *p_incl, *p_off, *p_cur, *p_part, *p_batch, *p_flag;
    cudaGetSymbolAddress((void**)&p_h,    g_h);
    cudaGetSymbolAddress((void**)&p_hn,   g_hn);
    cudaGetSymbolAddress((void**)&p_xl,   g_xl);
    cudaGetSymbolAddress((void**)&p_xr,   g_xr);
    cudaGetSymbolAddress((void**)&p_stats,g_stats);
    cudaGetSymbolAddress((void**)&p_src,  g_src);
    cudaGetSymbolAddress((void**)&p_dst,  g_dst);
    cudaGetSymbolAddress((void**)&p_csr,  g_csr);
    cudaGetSymbolAddress((void**)&p_deg,  g_deg);
    cudaGetSymbolAddress((void**)&p_incl, g_incl);
    cudaGetSymbolAddress((void**)&p_off,  g_off);
    cudaGetSymbolAddress((void**)&p_cur,  g_cur);
    cudaGetSymbolAddress((void**)&p_part, g_part);
    cudaGetSymbolAddress((void**)&p_batch,g_batch);
    cudaGetSymbolAddress((void**)&p_flag, g_is64);

    // dtype detect + CSR build (per call; edge_index is an input)
    detect_k<<<1, 256>>>(ei32, p_flag);
    cudaMemsetAsync(p_deg, 0, NN * sizeof(int));
    convert_hist_k<<<(EE + 255) / 256, 256>>>(ei32, p_flag, p_src, p_dst, p_deg, b32, p_batch);
    scanA_k<<<NB, 1024>>>(p_deg, p_incl, p_part);
    scanC_k<<<NB, 1024>>>(p_incl, p_part, p_deg, p_off, p_cur);
    scatter_k<<<(EE + 255) / 256, 256>>>(p_src, p_dst, p_cur, p_csr);

    // initial projection: h = x @ Wp (tf32 tensor cores)
    gemm_tf32_init_k<<<(NN + 127) / 128, 256>>>(x, Wp, p_h, NN);

    const int NCHUNK = (NN + 127) / 128;
    for (int l = 0; l < LL; l++) {
        float* slotCur  = p_stats + (l & 1) * 2;
        const float* slotPrev = p_stats + ((l + 1) & 1) * 2;
        const float* Ain = (l == 0) ? p_h : p_hn;
        gemm_tf32_k<<<NCHUNK, 256>>>(
            Ain, Wl + l * 64 * 256, Wr + l * 64 * 256,
            bl + l * 256, br + l * 256, p_xl, p_xr, NN,
            (l == 0) ? nullptr : slotPrev,
            (l == 0) ? nullptr : (lnw + (l - 1) * CC),
            (l == 0) ? nullptr : (lnb + (l - 1) * CC),
            slotCur);
        aggregate_k<<<(NN + 7) / 8, 256>>>(p_xl, p_xr, p_off, p_csr,
                                           att + l * HH * CC, cb + l * CC, p_hn, slotCur);
    }

    // final graph-norm + SELU (layer 3), then pool
    norm_k<<<(NN * 16 + 255) / 256, 256>>>((const float4*)p_hn, p_stats + ((LL - 1) & 1) * 2,
                                           lnw + (LL - 1) * CC, lnb + (LL - 1) * CC, (float4*)p_h);
    pool_k<<<GG, 256>>>(p_h, p_batch, Wh, bh, out);
}

// round 15
// speedup vs baseline: 1.1764x; 1.0036x over previous
#include <cuda_runtime.h>
#include <cuda_fp16.h>
#include <math.h>

#define NN 50000
#define FF 128
#define CC 64
#define HH 4
#define EE 500000
#define GG 32
#define LL 4
#define NB 49   // scan blocks = ceil(NN/1024)

// ---------------- scratch (static device globals; no allocation allowed) ----------
__device__ __align__(16) float  g_h [NN*CC];
__device__ __align__(16) float  g_hn[NN*CC];
__device__ __align__(16) __half g_xl[NN*HH*CC];
__device__ __align__(16) __half g_xr[NN*HH*CC];
__device__ int   g_src[EE];
__device__ int   g_dst[EE];
__device__ int   g_csr[EE];
__device__ int   g_deg[NN];
__device__ int   g_off[NN+1];
__device__ int   g_cur[NN];
__device__ int   g_part[64];
__device__ int   g_batch[NN];
__device__ int   g_is64;
__device__ int   g_bar;          // scan spin-barrier counter (reset each call)
__device__ float g_stats[4];     // two ping-pong slots of (sum, sumsq)

// ---------------- zero deg + dtype detect + barrier reset (one kernel) -------------
// int64 edge_index has zero odd 32-bit words; genuine int32 values almost never do.
__global__ void zero_detect_k(const int* __restrict__ ei32, int* __restrict__ flag,
                              int* __restrict__ deg, int* __restrict__ bar) {
    int i = blockIdx.x * blockDim.x + threadIdx.x;
    if (i < NN) deg[i] = 0;
    if (blockIdx.x == 0) {
        __shared__ int nz;
        if (threadIdx.x == 0) { nz = 0; *bar = 0; }
        __syncthreads();
        int v = ei32[threadIdx.x * 2 + 1];
        if (v != 0) atomicAdd(&nz, 1);
        __syncthreads();
        if (threadIdx.x == 0) *flag = (nz == 0) ? 1 : 0;
    }
}

__device__ __forceinline__ int clampN(int v) {
    return v < 0 ? 0 : (v >= NN ? NN - 1 : v);
}

// ---------------- edge prep (convert + degree histogram + batch convert fused) -----
__global__ void convert_hist_k(const int* __restrict__ ei32, const int* __restrict__ flag,
                               int* __restrict__ src, int* __restrict__ dst,
                               int* __restrict__ deg,
                               const int* __restrict__ b32, int* __restrict__ bout) {
    int i = blockIdx.x * blockDim.x + threadIdx.x;
    if (i >= EE) return;
    int f = *flag;
    int s, d;
    if (f) { s = ei32[2 * i];      d = ei32[2 * (EE + i)]; }
    else   { s = ei32[i];          d = ei32[EE + i]; }
    s = clampN(s); d = clampN(d);
    src[i] = s;
    dst[i] = d;
    atomicAdd(&deg[d], 1);
    if (i < NN) {
        int v = f ? b32[2 * i] : b32[i];
        bout[i] = v < 0 ? 0 : (v >= GG ? GG - 1 : v);
    }
}

// ---------------- single-pass exclusive scan over deg (merged scanA + scanC) -------
// 49 blocks, all resident simultaneously -> device spin barrier is safe.
// Inclusive scan stays in registers; only 49 block totals cross blocks.
__global__ void __launch_bounds__(1024) scan_k(
    const int* __restrict__ deg, int* __restrict__ part, int* __restrict__ bar,
    int* __restrict__ off, int* __restrict__ cur)
{
    __shared__ int s[1024];
    __shared__ int stmp[64];
    __shared__ int sbase;
    int t = threadIdx.x;
    int i = blockIdx.x * 1024 + t;
    int dv = (i < NN) ? deg[i] : 0;
    s[t] = dv;
    __syncthreads();
    for (int o = 1; o < 1024; o <<= 1) {
        int v = (t >= o) ? s[t - o] : 0;
        __syncthreads();
        s[t] += v;
        __syncthreads();
    }
    int incl = s[t];
    if (t == 1023) part[blockIdx.x] = s[1023];
    __threadfence();
    if (t == 0) {
        atomicAdd(bar, 1);
        while (atomicAdd(bar, 0) < NB) { }
    }
    __syncthreads();
    if (t < 64) stmp[t] = (t < blockIdx.x) ? part[t] : 0;
    __syncthreads();
    if (t < 32) {
        int v = stmp[t] + stmp[t + 32];
        #pragma unroll
        for (int o = 16; o >= 1; o >>= 1) v += __shfl_xor_sync(0xffffffffu, v, o);
        if (t == 0) sbase = v;
    }
    __syncthreads();
    if (i < NN) {
        int start = incl + sbase - dv;
        off[i] = start;
        cur[i] = start;
    }
    if (i == 0) off[NN] = EE;
}

__global__ void scatter_k(const int* __restrict__ src, const int* __restrict__ dst,
                          int* __restrict__ cur, int* __restrict__ csr) {
    int e = blockIdx.x * blockDim.x + threadIdx.x;
    if (e < EE) {
        int d = dst[e];
        int pos = atomicAdd(&cur[d], 1);
        csr[pos] = src[e];
    }
}

// ---------------- tf32 + selu helpers ----------------
__device__ __forceinline__ unsigned f2tf32(float v) {
    unsigned u;
    asm("cvt.rna.tf32.f32 %0, %1;" : "=r"(u) : "f"(v));
    return u;
}

__device__ __forceinline__ float selu_f(float x) {
    const float sc = 1.0507009873554805f, al = 1.6732632423543772f;
    return x > 0.f ? sc * x : sc * al * expm1f(x);
}

// ---------------- tf32 GEMM for layer projections: one block per 128-row chunk ------
// Stages A once (optional fused graph-norm + SELU), loops 8 output-column chunks.
// Block 0 zeroes this layer's stats slot for the following aggregate.
__global__ void __launch_bounds__(256) gemm_tf32_k(
    const float* __restrict__ A,
    const float* __restrict__ W0, const float* __restrict__ W1,
    const float* __restrict__ b0, const float* __restrict__ b1,
    __half* __restrict__ O0, __half* __restrict__ O1, int nrows,
    const float* __restrict__ normstats,
    const float* __restrict__ lw, const float* __restrict__ lb,
    float* __restrict__ zstats)
{
    __shared__ unsigned sA[128 * 68];

    const int t    = threadIdx.x;
    const int lane = t & 31;
    const int grp  = lane >> 2;
    const int qid  = lane & 3;
    const int wid  = t >> 5;
    const int warpM = wid & 3;
    const int warpN = wid >> 2;
    const int mbase = blockIdx.x * 128;

    if (blockIdx.x == 0 && t < 2) zstats[t] = 0.f;

    const int q = t & 15;
    float mean = 0.f, rstd = 1.f;
    float4 w4 = make_float4(1.f, 1.f, 1.f, 1.f), b4 = make_float4(0.f, 0.f, 0.f, 0.f);
    if (normstats) {
        const float invM = 1.f / ((float)NN * 64.f);
        mean = normstats[0] * invM;
        float var = normstats[1] * invM - mean * mean;
        rstd = 1.f / (sqrtf(fmaxf(var, 0.f)) + 1e-5f);
        w4 = *(const float4*)&lw[q * 4];
        b4 = *(const float4*)&lb[q * 4];
    }

    #pragma unroll
    for (int it = 0; it < 8; it++) {
        int idx = it * 256 + t;
        int r = idx >> 4;
        int gr = mbase + r;
        float4 v = make_float4(0.f, 0.f, 0.f, 0.f);
        if (gr < nrows) v = *(const float4*)&A[gr * 64 + q * 4];
        if (normstats) {
            v.x = selu_f((v.x - mean) * rstd * w4.x + b4.x);
            v.y = selu_f((v.y - mean) * rstd * w4.y + b4.y);
            v.z = selu_f((v.z - mean) * rstd * w4.z + b4.z);
            v.w = selu_f((v.w - mean) * rstd * w4.w + b4.w);
        }
        unsigned* dstp = &sA[r * 68 + q * 4];
        dstp[0] = f2tf32(v.x); dstp[1] = f2tf32(v.y);
        dstp[2] = f2tf32(v.z); dstp[3] = f2tf32(v.w);
    }
    __syncthreads();

    #pragma unroll 1
    for (int nc = 0; nc < 8; nc++) {
        const bool half1 = (nc >= 4);
        const float* Wb   = half1 ? W1 : W0;
        const float* bias = half1 ? b1 : b0;
        __half*      Ob   = half1 ? O1 : O0;
        const int nloc = (nc & 3) * 64 + warpN * 32;

        unsigned Breg[8][4][2];
        #pragma unroll
        for (int ks = 0; ks < 8; ks++) {
            #pragma unroll
            for (int nt = 0; nt < 4; nt++) {
                int col = nloc + nt * 8 + grp;
                Breg[ks][nt][0] = f2tf32(Wb[(ks * 8 + qid)     * 256 + col]);
                Breg[ks][nt][1] = f2tf32(Wb[(ks * 8 + qid + 4) * 256 + col]);
            }
        }

        float acc[2][4][4];
        #pragma unroll
        for (int mt = 0; mt < 2; mt++)
            #pragma unroll
            for (int nt = 0; nt < 4; nt++)
                #pragma unroll
                for (int c = 0; c < 4; c++) acc[mt][nt][c] = 0.f;

        #pragma unroll
        for (int ks = 0; ks < 8; ks++) {
            unsigned a[2][4];
            #pragma unroll
            for (int mt = 0; mt < 2; mt++) {
                int r0 = warpM * 32 + mt * 16 + grp;
                int c  = ks * 8 + qid;
                a[mt][0] = sA[r0 * 68 + c];
                a[mt][1] = sA[(r0 + 8) * 68 + c];
                a[mt][2] = sA[r0 * 68 + c + 4];
                a[mt][3] = sA[(r0 + 8) * 68 + c + 4];
            }
            #pragma unroll
            for (int mt = 0; mt < 2; mt++) {
                #pragma unroll
                for (int nt = 0; nt < 4; nt++) {
                    asm volatile(
                        "mma.sync.aligned.m16n8k8.row.col.f32.tf32.tf32.f32 "
                        "{%0,%1,%2,%3}, {%4,%5,%6,%7}, {%8,%9}, {%0,%1,%2,%3};"
                        : "+f"(acc[mt][nt][0]), "+f"(acc[mt][nt][1]),
                          "+f"(acc[mt][nt][2]), "+f"(acc[mt][nt][3])
                        : "r"(a[mt][0]), "r"(a[mt][1]), "r"(a[mt][2]), "r"(a[mt][3]),
                          "r"(Breg[ks][nt][0]), "r"(Breg[ks][nt][1]));
                }
            }
        }

        #pragma unroll
        for (int nt = 0; nt < 4; nt++) {
            int colw = nloc + nt * 8 + qid * 2;
            float bb0 = bias[colw], bb1 = bias[colw + 1];
            #pragma unroll
            for (int mt = 0; mt < 2; mt++) {
                int r0 = mbase + warpM * 32 + mt * 16 + grp;
                if (r0 < nrows)
                    *(__half2*)&Ob[r0 * 256 + colw] =
                        __floats2half2_rn(acc[mt][nt][0] + bb0, acc[mt][nt][1] + bb1);
                int r1 = r0 + 8;
                if (r1 < nrows)
                    *(__half2*)&Ob[r1 * 256 + colw] =
                        __floats2half2_rn(acc[mt][nt][2] + bb0, acc[mt][nt][3] + bb1);
            }
        }
    }
}

// ---------------- tf32 GEMM for initial projection (A[N,128] @ W[128,64]) ----------------
__global__ void __launch_bounds__(256) gemm_tf32_init_k(
    const float* __restrict__ A, const float* __restrict__ W,
    float* __restrict__ O, int nrows)
{
    __shared__ unsigned sA[128 * 68];

    const int t    = threadIdx.x;
    const int lane = t & 31;
    const int wid  = t >> 5;
    const int grp  = lane >> 2;
    const int qid  = lane & 3;
    const int warpM = wid & 3;
    const int warpN = wid >> 2;
    const int nloc = warpN * 32;
    const int mbase = blockIdx.x * 128;

    float acc[2][4][4];
    #pragma unroll
    for (int mt = 0; mt < 2; mt++)
        #pragma unroll
        for (int nt = 0; nt < 4; nt++)
            #pragma unroll
            for (int c = 0; c < 4; c++) acc[mt][nt][c] = 0.f;

    #pragma unroll
    for (int kc = 0; kc < 2; kc++) {
        unsigned Breg[8][4][2];
        #pragma unroll
        for (int ks = 0; ks < 8; ks++) {
            #pragma unroll
            for (int nt = 0; nt < 4; nt++) {
                int col = nloc + nt * 8 + grp;
                int row = kc * 64 + ks * 8;
                Breg[ks][nt][0] = f2tf32(W[(row + qid)     * 64 + col]);
                Breg[ks][nt][1] = f2tf32(W[(row + qid + 4) * 64 + col]);
            }
        }

        #pragma unroll
        for (int it = 0; it < 8; it++) {
            int idx = it * 256 + t;
            int r = idx >> 4, q = idx & 15;
            int gr = mbase + r;
            float4 v = make_float4(0.f, 0.f, 0.f, 0.f);
            if (gr < nrows) v = *(const float4*)&A[gr * 128 + kc * 64 + q * 4];
            unsigned* dstp = &sA[r * 68 + q * 4];
            dstp[0] = f2tf32(v.x); dstp[1] = f2tf32(v.y);
            dstp[2] = f2tf32(v.z); dstp[3] = f2tf32(v.w);
        }
        __syncthreads();

        #pragma unroll
        for (int ks = 0; ks < 8; ks++) {
            unsigned a[2][4];
            #pragma unroll
            for (int mt = 0; mt < 2; mt++) {
                int r0 = warpM * 32 + mt * 16 + grp;
                int c  = ks * 8 + qid;
                a[mt][0] = sA[r0 * 68 + c];
                a[mt][1] = sA[(r0 + 8) * 68 + c];
                a[mt][2] = sA[r0 * 68 + c + 4];
                a[mt][3] = sA[(r0 + 8) * 68 + c + 4];
            }
            #pragma unroll
            for (int mt = 0; mt < 2; mt++) {
                #pragma unroll
                for (int nt = 0; nt < 4; nt++) {
                    asm volatile(
                        "mma.sync.aligned.m16n8k8.row.col.f32.tf32.tf32.f32 "
                        "{%0,%1,%2,%3}, {%4,%5,%6,%7}, {%8,%9}, {%0,%1,%2,%3};"
                        : "+f"(acc[mt][nt][0]), "+f"(acc[mt][nt][1]),
                          "+f"(acc[mt][nt][2]), "+f"(acc[mt][nt][3])
                        : "r"(a[mt][0]), "r"(a[mt][1]), "r"(a[mt][2]), "r"(a[mt][3]),
                          "r"(Breg[ks][nt][0]), "r"(Breg[ks][nt][1]));
                }
            }
        }
        __syncthreads();
    }

    #pragma unroll
    for (int nt = 0; nt < 4; nt++) {
        int colw = nloc + nt * 8 + qid * 2;
        #pragma unroll
        for (int mt = 0; mt < 2; mt++) {
            int r0 = mbase + warpM * 32 + mt * 16 + grp;
            if (r0 < nrows)
                *(float2*)&O[r0 * 64 + colw] = make_float2(acc[mt][nt][0], acc[mt][nt][1]);
            int r1 = r0 + 8;
            if (r1 < nrows)
                *(float2*)&O[r1 * 64 + colw] = make_float2(acc[mt][nt][2], acc[mt][nt][3]);
        }
    }
}

// ---------------- GATv2 aggregate: 8 warps/block, fp16 feats, half2 math -----------
__global__ void __launch_bounds__(256) aggregate_k(
    const __half* __restrict__ xl, const __half* __restrict__ xr,
    const int* __restrict__ off, const int* __restrict__ csr,
    const float* __restrict__ att, const float* __restrict__ cb,
    float* __restrict__ hn, float* __restrict__ stats)
{
    int warp = threadIdx.x >> 5, lane = threadIdx.x & 31;
    int i = blockIdx.x * 8 + warp;
    __shared__ float ssum[2];
    if (threadIdx.x < 2) ssum[threadIdx.x] = 0.f;
    __syncthreads();

    if (i < NN) {
        const float4* xl4 = (const float4*)xl;
        const float4* xr4 = (const float4*)xr;
        __half2 rr2[4];
        {
            float4 rv = xr4[i * 32 + lane];
            const __half2* hp = (const __half2*)&rv;
            #pragma unroll
            for (int k = 0; k < 4; k++) rr2[k] = hp[k];
        }
        int head = lane >> 3, cg = lane & 7;
        __half2 att2[4];
        #pragma unroll
        for (int k = 0; k < 4; k++)
            att2[k] = __floats2half2_rn(att[head * 64 + cg * 8 + 2 * k],
                                        att[head * 64 + cg * 8 + 2 * k + 1]);
        const __half2 c02 = __float2half2_rn(0.2f);

        float d = 0.f;
        __half2 acc2[4];
        #pragma unroll
        for (int k = 0; k < 4; k++) acc2[k] = __float2half2_rn(0.f);
        int e0 = off[i], e1 = off[i + 1];

        float4 sa, sb;
        if (e0 < e1)     sa = xl4[csr[e0] * 32 + lane];
        if (e0 + 1 < e1) sb = xl4[csr[e0 + 1] * 32 + lane];
        for (int e = e0; e < e1; e++) {
            float4 cur = sa;
            sa = sb;
            if (e + 2 < e1) sb = xl4[csr[e + 2] * 32 + lane];

            const __half2* x2 = (const __half2*)&cur;
            __half2 p2 = __float2half2_rn(0.f);
            #pragma unroll
            for (int k = 0; k < 4; k++) {
                __half2 v2 = __hadd2(x2[k], rr2[k]);
                __half2 lv = __hmax2(v2, __hmul2(v2, c02));
                p2 = __hfma2(lv, att2[k], p2);
            }
            float2 pf = __half22float2(p2);
            float p = pf.x + pf.y;
            p += __shfl_xor_sync(0xffffffffu, p, 4);
            p += __shfl_xor_sync(0xffffffffu, p, 2);
            p += __shfl_xor_sync(0xffffffffu, p, 1);
            float w = __expf(fminf(p, 60.f));
            d += w;
            __half2 w2 = __float2half2_rn(w);
            #pragma unroll
            for (int k = 0; k < 4; k++) acc2[k] = __hfma2(w2, x2[k], acc2[k]);
        }
        float inv = (d > 0.f) ? 1.f / d : 0.f;
        float o[8];
        #pragma unroll
        for (int k = 0; k < 4; k++) {
            float2 f = __half22float2(acc2[k]);
            o[2 * k]     = f.x * inv;
            o[2 * k + 1] = f.y * inv;
        }
        #pragma unroll
        for (int j = 0; j < 8; j++) o[j] += __shfl_xor_sync(0xffffffffu, o[j], 8);
        #pragma unroll
        for (int j = 0; j < 8; j++) o[j] += __shfl_xor_sync(0xffffffffu, o[j], 16);
        float ls = 0.f, lq = 0.f;
        #pragma unroll
        for (int j = 0; j < 8; j++) {
            o[j] = o[j] * 0.25f + cb[cg * 8 + j];
            ls += o[j];
            lq += o[j] * o[j];
        }
        if (lane < 8) {
            float4* hn4 = (float4*)hn;
            hn4[i * 16 + lane * 2]     = make_float4(o[0], o[1], o[2], o[3]);
            hn4[i * 16 + lane * 2 + 1] = make_float4(o[4], o[5], o[6], o[7]);
        }
        #pragma unroll
        for (int ofs = 16; ofs >= 1; ofs >>= 1) {
            ls += __shfl_xor_sync(0xffffffffu, ls, ofs);
            lq += __shfl_xor_sync(0xffffffffu, lq, ofs);
        }
        if (lane == 0) {
            atomicAdd(&ssum[0], ls * 0.25f);
            atomicAdd(&ssum[1], lq * 0.25f);
        }
    }
    __syncthreads();
    if (threadIdx.x == 0) {
        atomicAdd(&stats[0], ssum[0]);
        atomicAdd(&stats[1], ssum[1]);
    }
}

// ---------------- global graph-norm + SELU (after final layer only) ----------------
__global__ void norm_k(const float4* __restrict__ hn, const float* __restrict__ stats,
                       const float* __restrict__ w, const float* __restrict__ b,
                       float4* __restrict__ h)
{
    int idx = blockIdx.x * blockDim.x + threadIdx.x;
    if (idx >= NN * 16) return;
    const float invM = 1.f / ((float)NN * 64.f);
    float mean = stats[0] * invM;
    float var  = stats[1] * invM - mean * mean;
    float rstd = 1.f / (sqrtf(fmaxf(var, 0.f)) + 1e-5f);
    int c = (idx * 4) & 63;
    float4 v = hn[idx];
    v.x = selu_f((v.x - mean) * rstd * w[c + 0] + b[c + 0]);
    v.y = selu_f((v.y - mean) * rstd * w[c + 1] + b[c + 1]);
    v.z = selu_f((v.z - mean) * rstd * w[c + 2] + b[c + 2]);
    v.w = selu_f((v.w - mean) * rstd * w[c + 3] + b[c + 3]);
    h[idx] = v;
}

// ---------------- mean pool per graph + head projection ----------------
__device__ __forceinline__ int lbound_i(const int* a, int n, int key) {
    int lo = 0, hi = n;
    while (lo < hi) {
        int m = (lo + hi) >> 1;
        if (a[m] < key) lo = m + 1; else hi = m;
    }
    return lo;
}

__global__ void pool_k(const float* __restrict__ h, const int* __restrict__ batch,
                       const float* __restrict__ Wh, const float* __restrict__ bh,
                       float* __restrict__ out)
{
    int g = blockIdx.x;
    __shared__ int slo, shi;
    __shared__ float sacc[4][64];
    __shared__ float sdot[64];
    int t = threadIdx.x;
    if (t == 0) {
        slo = lbound_i(batch, NN, g);
        shi = lbound_i(batch, NN, g + 1);
    }
    __syncthreads();
    int lo = slo, hi = shi;
    int c = t & 63, slot = t >> 6;
    float p = 0.f;
    for (int n = lo + slot; n < hi; n += 4) p += h[n * 64 + c];
    sacc[slot][c] = p;
    __syncthreads();
    if (slot == 0) {
        float tot = sacc[0][c] + sacc[1][c] + sacc[2][c] + sacc[3][c];
        float cnt = (float)((hi - lo) > 1 ? (hi - lo) : 1);
        sdot[c] = (tot / cnt) * Wh[c];
    }
    __syncthreads();
    if (t < 32) {
        float v = sdot[t] + sdot[t + 32];
        #pragma unroll
        for (int o = 16; o >= 1; o >>= 1) v += __shfl_xor_sync(0xffffffffu, v, o);
        if (t == 0) out[g] = v + bh[0];
    }
}

// ---------------- launch ----------------
extern "C" void kernel_launch(void* const* d_in, const int* in_sizes, int n_in,
                              void* d_out, int out_size)
{
    const float* x     = (const float*)d_in[0];
    const int*   ei32  = (const int*)d_in[1];   // int32 or int64 (auto-detected)
    const int*   b32   = (const int*)d_in[2];
    const float* Wp    = (const float*)d_in[3];
    const float* Wl    = (const float*)d_in[4];
    const float* bl    = (const float*)d_in[5];
    const float* Wr    = (const float*)d_in[6];
    const float* br    = (const float*)d_in[7];
    const float* att   = (const float*)d_in[8];
    const float* cb    = (const float*)d_in[9];
    const float* lnw   = (const float*)d_in[10];
    const float* lnb   = (const float*)d_in[11];
    const float* Wh    = (const float*)d_in[12];
    const float* bh    = (const float*)d_in[13];
    float* out = (float*)d_out;

    float *p_h, *p_hn, *p_stats;
    __half *p_xl, *p_xr;
    int *p_src, *p_dst, *p_csr, *p_deg, *p_off, *p_cur, *p_part, *p_batch, *p_flag, *p_bar;
    cudaGetSymbolAddress((void**)&p_h,    g_h);
    cudaGetSymbolAddress((void**)&p_hn,   g_hn);
    cudaGetSymbolAddress((void**)&p_xl,   g_xl);
    cudaGetSymbolAddress((void**)&p_xr,   g_xr);
    cudaGetSymbolAddress((void**)&p_stats,g_stats);
    cudaGetSymbolAddress((void**)&p_src,  g_src);
    cudaGetSymbolAddress((void**)&p_dst,  g_dst);
    cudaGetSymbolAddress((void**)&p_csr,  g_csr);
    cudaGetSymbolAddress((void**)&p_deg,  g_deg);
    cudaGetSymbolAddress((void**)&p_off,  g_off);
    cudaGetSymbolAddress((void**)&p_cur,  g_cur);
    cudaGetSymbolAddress((void**)&p_part, g_part);
    cudaGetSymbolAddress((void**)&p_batch,g_batch);
    cudaGetSymbolAddress((void**)&p_flag, g_is64);
    cudaGetSymbolAddress((void**)&p_bar,  g_bar);

    // dtype detect + CSR build (per call; edge_index is an input)
    zero_detect_k<<<(NN + 255) / 256, 256>>>(ei32, p_flag, p_deg, p_bar);
    convert_hist_k<<<(EE + 255) / 256, 256>>>(ei32, p_flag, p_src, p_dst, p_deg, b32, p_batch);
    scan_k<<<NB, 1024>>>(p_deg, p_part, p_bar, p_off, p_cur);
    scatter_k<<<(EE + 255) / 256, 256>>>(p_src, p_dst, p_cur, p_csr);

    // initial projection: h = x @ Wp (tf32 tensor cores)
    gemm_tf32_init_k<<<(NN + 127) / 128, 256>>>(x, Wp, p_h, NN);

    const int NCHUNK = (NN + 127) / 128;
    for (int l = 0; l < LL; l++) {
        float* slotCur  = p_stats + (l & 1) * 2;
        const float* slotPrev = p_stats + ((l + 1) & 1) * 2;
        const float* Ain = (l == 0) ? p_h : p_hn;
        gemm_tf32_k<<<NCHUNK, 256>>>(
            Ain, Wl + l * 64 * 256, Wr + l * 64 * 256,
            bl + l * 256, br + l * 256, p_xl, p_xr, NN,
            (l == 0) ? nullptr : slotPrev,
            (l == 0) ? nullptr : (lnw + (l - 1) * CC),
            (l == 0) ? nullptr : (lnb + (l - 1) * CC),
            slotCur);
        aggregate_k<<<(NN + 7) / 8, 256>>>(p_xl, p_xr, p_off, p_csr,
                                           att + l * HH * CC, cb + l * CC, p_hn, slotCur);
    }

    // final graph-norm + SELU (layer 3), then pool
    norm_k<<<(NN * 16 + 255) / 256, 256>>>((const float4*)p_hn, p_stats + ((LL - 1) & 1) * 2,
                                           lnw + (LL - 1) * CC, lnb + (LL - 1) * CC, (float4*)p_h);
    pool_k<<<GG, 256>>>(p_h, p_batch, Wh, bh, out);
}

// round 16
// speedup vs baseline: 1.1799x; 1.0030x over previous
#include <cuda_runtime.h>
#include <cuda_fp16.h>
#include <math.h>

#define NN 50000
#define FF 128
#define CC 64
#define HH 4
#define EE 500000
#define GG 32
#define LL 4
#define NB 49   // scan blocks = ceil(NN/1024)

// ---------------- scratch (static device globals; no allocation allowed) ----------
__device__ __align__(16) float  g_h [NN*CC];
__device__ __align__(16) float  g_hn[NN*CC];
__device__ __align__(16) __half g_xl[NN*HH*CC];
__device__ __align__(16) __half g_xr[NN*HH*CC];
__device__ int   g_src[EE];
__device__ int   g_dst[EE];
__device__ int   g_rank[EE];
__device__ int   g_csr[EE];
__device__ int   g_deg[NN];
__device__ int   g_off[NN+1];
__device__ int   g_part[64];
__device__ int   g_batch[NN];
__device__ int   g_is64;
__device__ int   g_bar;          // scan spin-barrier counter (reset each call)
__device__ float g_stats[4];     // two ping-pong slots of (sum, sumsq)

// ---------------- zero deg + dtype detect + barrier reset (one kernel) -------------
// int64 edge_index has zero odd 32-bit words; genuine int32 values almost never do.
__global__ void zero_detect_k(const int* __restrict__ ei32, int* __restrict__ flag,
                              int* __restrict__ deg, int* __restrict__ bar) {
    int i = blockIdx.x * blockDim.x + threadIdx.x;
    if (i < NN) deg[i] = 0;
    if (blockIdx.x == 0) {
        __shared__ int nz;
        if (threadIdx.x == 0) { nz = 0; *bar = 0; }
        __syncthreads();
        int v = ei32[threadIdx.x * 2 + 1];
        if (v != 0) atomicAdd(&nz, 1);
        __syncthreads();
        if (threadIdx.x == 0) *flag = (nz == 0) ? 1 : 0;
    }
}

__device__ __forceinline__ int clampN(int v) {
    return v < 0 ? 0 : (v >= NN ? NN - 1 : v);
}

// ---------------- edge prep: convert + histogram; atomic return value = edge rank ---
__global__ void convert_hist_k(const int* __restrict__ ei32, const int* __restrict__ flag,
                               int* __restrict__ src, int* __restrict__ dst,
                               int* __restrict__ rank, int* __restrict__ deg,
                               const int* __restrict__ b32, int* __restrict__ bout) {
    int i = blockIdx.x * blockDim.x + threadIdx.x;
    if (i >= EE) return;
    int f = *flag;
    int s, d;
    if (f) { s = ei32[2 * i];      d = ei32[2 * (EE + i)]; }
    else   { s = ei32[i];          d = ei32[EE + i]; }
    s = clampN(s); d = clampN(d);
    src[i] = s;
    dst[i] = d;
    rank[i] = atomicAdd(&deg[d], 1);   // rank within destination bucket (free)
    if (i < NN) {
        int v = f ? b32[2 * i] : b32[i];
        bout[i] = v < 0 ? 0 : (v >= GG ? GG - 1 : v);
    }
}

// ---------------- single-pass exclusive scan over deg (device spin barrier) --------
// 49 blocks, all resident simultaneously -> spin barrier is safe.
__global__ void __launch_bounds__(1024) scan_k(
    const int* __restrict__ deg, int* __restrict__ part, int* __restrict__ bar,
    int* __restrict__ off)
{
    __shared__ int s[1024];
    __shared__ int stmp[64];
    __shared__ int sbase;
    int t = threadIdx.x;
    int i = blockIdx.x * 1024 + t;
    int dv = (i < NN) ? deg[i] : 0;
    s[t] = dv;
    __syncthreads();
    for (int o = 1; o < 1024; o <<= 1) {
        int v = (t >= o) ? s[t - o] : 0;
        __syncthreads();
        s[t] += v;
        __syncthreads();
    }
    int incl = s[t];
    if (t == 1023) part[blockIdx.x] = s[1023];
    __threadfence();
    if (t == 0) {
        atomicAdd(bar, 1);
        while (atomicAdd(bar, 0) < NB) { }
    }
    __syncthreads();
    if (t < 64) stmp[t] = (t < blockIdx.x) ? part[t] : 0;
    __syncthreads();
    if (t < 32) {
        int v = stmp[t] + stmp[t + 32];
        #pragma unroll
        for (int o = 16; o >= 1; o >>= 1) v += __shfl_xor_sync(0xffffffffu, v, o);
        if (t == 0) sbase = v;
    }
    __syncthreads();
    if (i < NN) off[i] = incl + sbase - dv;
    if (i == 0) off[NN] = EE;
}

// ---------------- scatter: NO atomics — position = off[dst] + precomputed rank -----
__global__ void scatter_k(const int* __restrict__ src, const int* __restrict__ dst,
                          const int* __restrict__ rank, const int* __restrict__ off,
                          int* __restrict__ csr) {
    int e = blockIdx.x * blockDim.x + threadIdx.x;
    if (e < EE) csr[off[dst[e]] + rank[e]] = src[e];
}

// ---------------- tf32 + selu helpers ----------------
__device__ __forceinline__ unsigned f2tf32(float v) {
    unsigned u;
    asm("cvt.rna.tf32.f32 %0, %1;" : "=r"(u) : "f"(v));
    return u;
}

__device__ __forceinline__ float selu_f(float x) {
    const float sc = 1.0507009873554805f, al = 1.6732632423543772f;
    return x > 0.f ? sc * x : sc * al * expm1f(x);
}

// ---------------- tf32 GEMM for layer projections: one block per 128-row chunk ------
// Stages A once (optional fused graph-norm + SELU), loops 8 output-column chunks.
// Block 0 zeroes this layer's stats slot for the following aggregate.
__global__ void __launch_bounds__(256) gemm_tf32_k(
    const float* __restrict__ A,
    const float* __restrict__ W0, const float* __restrict__ W1,
    const float* __restrict__ b0, const float* __restrict__ b1,
    __half* __restrict__ O0, __half* __restrict__ O1, int nrows,
    const float* __restrict__ normstats,
    const float* __restrict__ lw, const float* __restrict__ lb,
    float* __restrict__ zstats)
{
    __shared__ unsigned sA[128 * 68];

    const int t    = threadIdx.x;
    const int lane = t & 31;
    const int grp  = lane >> 2;
    const int qid  = lane & 3;
    const int wid  = t >> 5;
    const int warpM = wid & 3;
    const int warpN = wid >> 2;
    const int mbase = blockIdx.x * 128;

    if (blockIdx.x == 0 && t < 2) zstats[t] = 0.f;

    const int q = t & 15;
    float mean = 0.f, rstd = 1.f;
    float4 w4 = make_float4(1.f, 1.f, 1.f, 1.f), b4 = make_float4(0.f, 0.f, 0.f, 0.f);
    if (normstats) {
        const float invM = 1.f / ((float)NN * 64.f);
        mean = normstats[0] * invM;
        float var = normstats[1] * invM - mean * mean;
        rstd = 1.f / (sqrtf(fmaxf(var, 0.f)) + 1e-5f);
        w4 = *(const float4*)&lw[q * 4];
        b4 = *(const float4*)&lb[q * 4];
    }

    #pragma unroll
    for (int it = 0; it < 8; it++) {
        int idx = it * 256 + t;
        int r = idx >> 4;
        int gr = mbase + r;
        float4 v = make_float4(0.f, 0.f, 0.f, 0.f);
        if (gr < nrows) v = *(const float4*)&A[gr * 64 + q * 4];
        if (normstats) {
            v.x = selu_f((v.x - mean) * rstd * w4.x + b4.x);
            v.y = selu_f((v.y - mean) * rstd * w4.y + b4.y);
            v.z = selu_f((v.z - mean) * rstd * w4.z + b4.z);
            v.w = selu_f((v.w - mean) * rstd * w4.w + b4.w);
        }
        unsigned* dstp = &sA[r * 68 + q * 4];
        dstp[0] = f2tf32(v.x); dstp[1] = f2tf32(v.y);
        dstp[2] = f2tf32(v.z); dstp[3] = f2tf32(v.w);
    }
    __syncthreads();

    #pragma unroll 1
    for (int nc = 0; nc < 8; nc++) {
        const bool half1 = (nc >= 4);
        const float* Wb   = half1 ? W1 : W0;
        const float* bias = half1 ? b1 : b0;
        __half*      Ob   = half1 ? O1 : O0;
        const int nloc = (nc & 3) * 64 + warpN * 32;

        unsigned Breg[8][4][2];
        #pragma unroll
        for (int ks = 0; ks < 8; ks++) {
            #pragma unroll
            for (int nt = 0; nt < 4; nt++) {
                int col = nloc + nt * 8 + grp;
                Breg[ks][nt][0] = f2tf32(Wb[(ks * 8 + qid)     * 256 + col]);
                Breg[ks][nt][1] = f2tf32(Wb[(ks * 8 + qid + 4) * 256 + col]);
            }
        }

        float acc[2][4][4];
        #pragma unroll
        for (int mt = 0; mt < 2; mt++)
            #pragma unroll
            for (int nt = 0; nt < 4; nt++)
                #pragma unroll
                for (int c = 0; c < 4; c++) acc[mt][nt][c] = 0.f;

        #pragma unroll
        for (int ks = 0; ks < 8; ks++) {
            unsigned a[2][4];
            #pragma unroll
            for (int mt = 0; mt < 2; mt++) {
                int r0 = warpM * 32 + mt * 16 + grp;
                int c  = ks * 8 + qid;
                a[mt][0] = sA[r0 * 68 + c];
                a[mt][1] = sA[(r0 + 8) * 68 + c];
                a[mt][2] = sA[r0 * 68 + c + 4];
                a[mt][3] = sA[(r0 + 8) * 68 + c + 4];
            }
            #pragma unroll
            for (int mt = 0; mt < 2; mt++) {
                #pragma unroll
                for (int nt = 0; nt < 4; nt++) {
                    asm volatile(
                        "mma.sync.aligned.m16n8k8.row.col.f32.tf32.tf32.f32 "
                        "{%0,%1,%2,%3}, {%4,%5,%6,%7}, {%8,%9}, {%0,%1,%2,%3};"
                        : "+f"(acc[mt][nt][0]), "+f"(acc[mt][nt][1]),
                          "+f"(acc[mt][nt][2]), "+f"(acc[mt][nt][3])
                        : "r"(a[mt][0]), "r"(a[mt][1]), "r"(a[mt][2]), "r"(a[mt][3]),
                          "r"(Breg[ks][nt][0]), "r"(Breg[ks][nt][1]));
                }
            }
        }

        #pragma unroll
        for (int nt = 0; nt < 4; nt++) {
            int colw = nloc + nt * 8 + qid * 2;
            float bb0 = bias[colw], bb1 = bias[colw + 1];
            #pragma unroll
            for (int mt = 0; mt < 2; mt++) {
                int r0 = mbase + warpM * 32 + mt * 16 + grp;
                if (r0 < nrows)
                    *(__half2*)&Ob[r0 * 256 + colw] =
                        __floats2half2_rn(acc[mt][nt][0] + bb0, acc[mt][nt][1] + bb1);
                int r1 = r0 + 8;
                if (r1 < nrows)
                    *(__half2*)&Ob[r1 * 256 + colw] =
                        __floats2half2_rn(acc[mt][nt][2] + bb0, acc[mt][nt][3] + bb1);
            }
        }
    }
}

// ---------------- tf32 GEMM for initial projection (A[N,128] @ W[128,64]) ----------------
__global__ void __launch_bounds__(256) gemm_tf32_init_k(
    const float* __restrict__ A, const float* __restrict__ W,
    float* __restrict__ O, int nrows)
{
    __shared__ unsigned sA[128 * 68];

    const int t    = threadIdx.x;
    const int lane = t & 31;
    const int wid  = t >> 5;
    const int grp  = lane >> 2;
    const int qid  = lane & 3;
    const int warpM = wid & 3;
    const int warpN = wid >> 2;
    const int nloc = warpN * 32;
    const int mbase = blockIdx.x * 128;

    float acc[2][4][4];
    #pragma unroll
    for (int mt = 0; mt < 2; mt++)
        #pragma unroll
        for (int nt = 0; nt < 4; nt++)
            #pragma unroll
            for (int c = 0; c < 4; c++) acc[mt][nt][c] = 0.f;

    #pragma unroll
    for (int kc = 0; kc < 2; kc++) {
        unsigned Breg[8][4][2];
        #pragma unroll
        for (int ks = 0; ks < 8; ks++) {
            #pragma unroll
            for (int nt = 0; nt < 4; nt++) {
                int col = nloc + nt * 8 + grp;
                int row = kc * 64 + ks * 8;
                Breg[ks][nt][0] = f2tf32(W[(row + qid)     * 64 + col]);
                Breg[ks][nt][1] = f2tf32(W[(row + qid + 4) * 64 + col]);
            }
        }

        #pragma unroll
        for (int it = 0; it < 8; it++) {
            int idx = it * 256 + t;
            int r = idx >> 4, q = idx & 15;
            int gr = mbase + r;
            float4 v = make_float4(0.f, 0.f, 0.f, 0.f);
            if (gr < nrows) v = *(const float4*)&A[gr * 128 + kc * 64 + q * 4];
            unsigned* dstp = &sA[r * 68 + q * 4];
            dstp[0] = f2tf32(v.x); dstp[1] = f2tf32(v.y);
            dstp[2] = f2tf32(v.z); dstp[3] = f2tf32(v.w);
        }
        __syncthreads();

        #pragma unroll
        for (int ks = 0; ks < 8; ks++) {
            unsigned a[2][4];
            #pragma unroll
            for (int mt = 0; mt < 2; mt++) {
                int r0 = warpM * 32 + mt * 16 + grp;
                int c  = ks * 8 + qid;
                a[mt][0] = sA[r0 * 68 + c];
                a[mt][1] = sA[(r0 + 8) * 68 + c];
                a[mt][2] = sA[r0 * 68 + c + 4];
                a[mt][3] = sA[(r0 + 8) * 68 + c + 4];
            }
            #pragma unroll
            for (int mt = 0; mt < 2; mt++) {
                #pragma unroll
                for (int nt = 0; nt < 4; nt++) {
                    asm volatile(
                        "mma.sync.aligned.m16n8k8.row.col.f32.tf32.tf32.f32 "
                        "{%0,%1,%2,%3}, {%4,%5,%6,%7}, {%8,%9}, {%0,%1,%2,%3};"
                        : "+f"(acc[mt][nt][0]), "+f"(acc[mt][nt][1]),
                          "+f"(acc[mt][nt][2]), "+f"(acc[mt][nt][3])
                        : "r"(a[mt][0]), "r"(a[mt][1]), "r"(a[mt][2]), "r"(a[mt][3]),
                          "r"(Breg[ks][nt][0]), "r"(Breg[ks][nt][1]));
                }
            }
        }
        __syncthreads();
    }

    #pragma unroll
    for (int nt = 0; nt < 4; nt++) {
        int colw = nloc + nt * 8 + qid * 2;
        #pragma unroll
        for (int mt = 0; mt < 2; mt++) {
            int r0 = mbase + warpM * 32 + mt * 16 + grp;
            if (r0 < nrows)
                *(float2*)&O[r0 * 64 + colw] = make_float2(acc[mt][nt][0], acc[mt][nt][1]);
            int r1 = r0 + 8;
            if (r1 < nrows)
                *(float2*)&O[r1 * 64 + colw] = make_float2(acc[mt][nt][2], acc[mt][nt][3]);
        }
    }
}

// ---------------- GATv2 aggregate: 8 warps/block, fp16 feats, half2 math -----------
__global__ void __launch_bounds__(256) aggregate_k(
    const __half* __restrict__ xl, const __half* __restrict__ xr,
    const int* __restrict__ off, const int* __restrict__ csr,
    const float* __restrict__ att, const float* __restrict__ cb,
    float* __restrict__ hn, float* __restrict__ stats)
{
    int warp = threadIdx.x >> 5, lane = threadIdx.x & 31;
    int i = blockIdx.x * 8 + warp;
    __shared__ float ssum[2];
    if (threadIdx.x < 2) ssum[threadIdx.x] = 0.f;
    __syncthreads();

    if (i < NN) {
        const float4* xl4 = (const float4*)xl;
        const float4* xr4 = (const float4*)xr;
        __half2 rr2[4];
        {
            float4 rv = xr4[i * 32 + lane];
            const __half2* hp = (const __half2*)&rv;
            #pragma unroll
            for (int k = 0; k < 4; k++) rr2[k] = hp[k];
        }
        int head = lane >> 3, cg = lane & 7;
        __half2 att2[4];
        #pragma unroll
        for (int k = 0; k < 4; k++)
            att2[k] = __floats2half2_rn(att[head * 64 + cg * 8 + 2 * k],
                                        att[head * 64 + cg * 8 + 2 * k + 1]);
        const __half2 c02 = __float2half2_rn(0.2f);

        float d = 0.f;
        __half2 acc2[4];
        #pragma unroll
        for (int k = 0; k < 4; k++) acc2[k] = __float2half2_rn(0.f);
        int e0 = off[i], e1 = off[i + 1];

        float4 sa, sb;
        if (e0 < e1)     sa = xl4[csr[e0] * 32 + lane];
        if (e0 + 1 < e1) sb = xl4[csr[e0 + 1] * 32 + lane];
        for (int e = e0; e < e1; e++) {
            float4 cur = sa;
            sa = sb;
            if (e + 2 < e1) sb = xl4[csr[e + 2] * 32 + lane];

            const __half2* x2 = (const __half2*)&cur;
            __half2 p2 = __float2half2_rn(0.f);
            #pragma unroll
            for (int k = 0; k < 4; k++) {
                __half2 v2 = __hadd2(x2[k], rr2[k]);
                __half2 lv = __hmax2(v2, __hmul2(v2, c02));
                p2 = __hfma2(lv, att2[k], p2);
            }
            float2 pf = __half22float2(p2);
            float p = pf.x + pf.y;
            p += __shfl_xor_sync(0xffffffffu, p, 4);
            p += __shfl_xor_sync(0xffffffffu, p, 2);
            p += __shfl_xor_sync(0xffffffffu, p, 1);
            float w = __expf(fminf(p, 60.f));
            d += w;
            __half2 w2 = __float2half2_rn(w);
            #pragma unroll
            for (int k = 0; k < 4; k++) acc2[k] = __hfma2(w2, x2[k], acc2[k]);
        }
        float inv = (d > 0.f) ? 1.f / d : 0.f;
        float o[8];
        #pragma unroll
        for (int k = 0; k < 4; k++) {
            float2 f = __half22float2(acc2[k]);
            o[2 * k]     = f.x * inv;
            o[2 * k + 1] = f.y * inv;
        }
        #pragma unroll
        for (int j = 0; j < 8; j++) o[j] += __shfl_xor_sync(0xffffffffu, o[j], 8);
        #pragma unroll
        for (int j = 0; j < 8; j++) o[j] += __shfl_xor_sync(0xffffffffu, o[j], 16);
        float ls = 0.f, lq = 0.f;
        #pragma unroll
        for (int j = 0; j < 8; j++) {
            o[j] = o[j] * 0.25f + cb[cg * 8 + j];
            ls += o[j];
            lq += o[j] * o[j];
        }
        if (lane < 8) {
            float4* hn4 = (float4*)hn;
            hn4[i * 16 + lane * 2]     = make_float4(o[0], o[1], o[2], o[3]);
            hn4[i * 16 + lane * 2 + 1] = make_float4(o[4], o[5], o[6], o[7]);
        }
        #pragma unroll
        for (int ofs = 16; ofs >= 1; ofs >>= 1) {
            ls += __shfl_xor_sync(0xffffffffu, ls, ofs);
            lq += __shfl_xor_sync(0xffffffffu, lq, ofs);
        }
        if (lane == 0) {
            atomicAdd(&ssum[0], ls * 0.25f);
            atomicAdd(&ssum[1], lq * 0.25f);
        }
    }
    __syncthreads();
    if (threadIdx.x == 0) {
        atomicAdd(&stats[0], ssum[0]);
        atomicAdd(&stats[1], ssum[1]);
    }
}

// ---------------- global graph-norm + SELU (after final layer only) ----------------
__global__ void norm_k(const float4* __restrict__ hn, const float* __restrict__ stats,
                       const float* __restrict__ w, const float* __restrict__ b,
                       float4* __restrict__ h)
{
    int idx = blockIdx.x * blockDim.x + threadIdx.x;
    if (idx >= NN * 16) return;
    const float invM = 1.f / ((float)NN * 64.f);
    float mean = stats[0] * invM;
    float var  = stats[1] * invM - mean * mean;
    float rstd = 1.f / (sqrtf(fmaxf(var, 0.f)) + 1e-5f);
    int c = (idx * 4) & 63;
    float4 v = hn[idx];
    v.x = selu_f((v.x - mean) * rstd * w[c + 0] + b[c + 0]);
    v.y = selu_f((v.y - mean) * rstd * w[c + 1] + b[c + 1]);
    v.z = selu_f((v.z - mean) * rstd * w[c + 2] + b[c + 2]);
    v.w = selu_f((v.w - mean) * rstd * w[c + 3] + b[c + 3]);
    h[idx] = v;
}

// ---------------- mean pool per graph + head projection ----------------
__device__ __forceinline__ int lbound_i(const int* a, int n, int key) {
    int lo = 0, hi = n;
    while (lo < hi) {
        int m = (lo + hi) >> 1;
        if (a[m] < key) lo = m + 1; else hi = m;
    }
    return lo;
}

__global__ void pool_k(const float* __restrict__ h, const int* __restrict__ batch,
                       const float* __restrict__ Wh, const float* __restrict__ bh,
                       float* __restrict__ out)
{
    int g = blockIdx.x;
    __shared__ int slo, shi;
    __shared__ float sacc[4][64];
    __shared__ float sdot[64];
    int t = threadIdx.x;
    if (t == 0) {
        slo = lbound_i(batch, NN, g);
        shi = lbound_i(batch, NN, g + 1);
    }
    __syncthreads();
    int lo = slo, hi = shi;
    int c = t & 63, slot = t >> 6;
    float p = 0.f;
    for (int n = lo + slot; n < hi; n += 4) p += h[n * 64 + c];
    sacc[slot][c] = p;
    __syncthreads();
    if (slot == 0) {
        float tot = sacc[0][c] + sacc[1][c] + sacc[2][c] + sacc[3][c];
        float cnt = (float)((hi - lo) > 1 ? (hi - lo) : 1);
        sdot[c] = (tot / cnt) * Wh[c];
    }
    __syncthreads();
    if (t < 32) {
        float v = sdot[t] + sdot[t + 32];
        #pragma unroll
        for (int o = 16; o >= 1; o >>= 1) v += __shfl_xor_sync(0xffffffffu, v, o);
        if (t == 0) out[g] = v + bh[0];
    }
}

// ---------------- launch ----------------
extern "C" void kernel_launch(void* const* d_in, const int* in_sizes, int n_in,
                              void* d_out, int out_size)
{
    const float* x     = (const float*)d_in[0];
    const int*   ei32  = (const int*)d_in[1];   // int32 or int64 (auto-detected)
    const int*   b32   = (const int*)d_in[2];
    const float* Wp    = (const float*)d_in[3];
    const float* Wl    = (const float*)d_in[4];
    const float* bl    = (const float*)d_in[5];
    const float* Wr    = (const float*)d_in[6];
    const float* br    = (const float*)d_in[7];
    const float* att   = (const float*)d_in[8];
    const float* cb    = (const float*)d_in[9];
    const float* lnw   = (const float*)d_in[10];
    const float* lnb   = (const float*)d_in[11];
    const float* Wh    = (const float*)d_in[12];
    const float* bh    = (const float*)d_in[13];
    float* out = (float*)d_out;

    float *p_h, *p_hn, *p_stats;
    __half *p_xl, *p_xr;
    int *p_src, *p_dst, *p_rank, *p_csr, *p_deg, *p_off, *p_part, *p_batch, *p_flag, *p_bar;
    cudaGetSymbolAddress((void**)&p_h,    g_h);
    cudaGetSymbolAddress((void**)&p_hn,   g_hn);
    cudaGetSymbolAddress((void**)&p_xl,   g_xl);
    cudaGetSymbolAddress((void**)&p_xr,   g_xr);
    cudaGetSymbolAddress((void**)&p_stats,g_stats);
    cudaGetSymbolAddress((void**)&p_src,  g_src);
    cudaGetSymbolAddress((void**)&p_dst,  g_dst);
    cudaGetSymbolAddress((void**)&p_rank, g_rank);
    cudaGetSymbolAddress((void**)&p_csr,  g_csr);
    cudaGetSymbolAddress((void**)&p_deg,  g_deg);
    cudaGetSymbolAddress((void**)&p_off,  g_off);
    cudaGetSymbolAddress((void**)&p_part, g_part);
    cudaGetSymbolAddress((void**)&p_batch,g_batch);
    cudaGetSymbolAddress((void**)&p_flag, g_is64);
    cudaGetSymbolAddress((void**)&p_bar,  g_bar);

    // dtype detect + CSR build (per call; edge_index is an input)
    zero_detect_k<<<(NN + 255) / 256, 256>>>(ei32, p_flag, p_deg, p_bar);
    convert_hist_k<<<(EE + 255) / 256, 256>>>(ei32, p_flag, p_src, p_dst, p_rank, p_deg, b32, p_batch);
    scan_k<<<NB, 1024>>>(p_deg, p_part, p_bar, p_off);
    scatter_k<<<(EE + 255) / 256, 256>>>(p_src, p_dst, p_rank, p_off, p_csr);

    // initial projection: h = x @ Wp (tf32 tensor cores)
    gemm_tf32_init_k<<<(NN + 127) / 128, 256>>>(x, Wp, p_h, NN);

    const int NCHUNK = (NN + 127) / 128;
    for (int l = 0; l < LL; l++) {
        float* slotCur  = p_stats + (l & 1) * 2;
        const float* slotPrev = p_stats + ((l + 1) & 1) * 2;
        const float* Ain = (l == 0) ? p_h : p_hn;
        gemm_tf32_k<<<NCHUNK, 256>>>(
            Ain, Wl + l * 64 * 256, Wr + l * 64 * 256,
            bl + l * 256, br + l * 256, p_xl, p_xr, NN,
            (l == 0) ? nullptr : slotPrev,
            (l == 0) ? nullptr : (lnw + (l - 1) * CC),
            (l == 0) ? nullptr : (lnb + (l - 1) * CC),
            slotCur);
        aggregate_k<<<(NN + 7) / 8, 256>>>(p_xl, p_xr, p_off, p_csr,
                                           att + l * HH * CC, cb + l * CC, p_hn, slotCur);
    }

    // final graph-norm + SELU (layer 3), then pool
    norm_k<<<(NN * 16 + 255) / 256, 256>>>((const float4*)p_hn, p_stats + ((LL - 1) & 1) * 2,
                                           lnw + (LL - 1) * CC, lnb + (LL - 1) * CC, (float4*)p_h);
    pool_k<<<GG, 256>>>(p_h, p_batch, Wh, bh, out);
}